// round 1
// baseline (speedup 1.0000x reference)
#include <cuda_runtime.h>
#include <math.h>

#define B_  8
#define N_  1024
#define D_  256
#define H_  8
#define DH_ 32
#define R_  4
#define FF_ 1024
#define M_  (B_*N_)   // 8192 rows

// ---- scratch (device globals: no allocations allowed) ----
__device__ float g_Q[M_*D_];
__device__ float g_K[M_*D_];
__device__ float g_V[(size_t)M_*R_*D_];   // layout: [b*N+n][r*256 + c]
__device__ float g_O[M_*D_];
__device__ float g_T1[M_*D_];
__device__ float g_X[M_*D_];
__device__ float g_F1[(size_t)M_*FF_];
__device__ float g_T2[M_*D_];

__device__ __forceinline__ float gelu_f(float x){
    return 0.5f*x*(1.0f + erff(x*0.70710678118654752440f));
}

// ---------------- generic fp32 tiled GEMM: C = A(MxK) @ B(KxN) + bias, opt GELU ----------------
// BM=BN=64, BK=16, 256 threads, 4x4 per thread. All dims divisible (M=8192, N in {256,1024}, K in {256,1024}).
template<bool GELU>
__global__ void __launch_bounds__(256) gemm_kernel(
    const float* __restrict__ A, const float* __restrict__ Bm,
    const float* __restrict__ bias, float* __restrict__ C,
    int Ncols, int K, int ldc)
{
    __shared__ float As[16][64];
    __shared__ float Bs[16][64];
    const int t  = threadIdx.x;
    const int tx = t & 15, ty = t >> 4;
    const int row0 = blockIdx.y*64, col0 = blockIdx.x*64;
    const int lm = t>>2, lk4 = (t&3)*4;       // A-load mapping
    const int lbk = t>>4, lbn = (t&15)*4;     // B-load mapping
    float acc[4][4] = {};

    for (int k0 = 0; k0 < K; k0 += 16){
        float4 a = *(const float4*)&A[(size_t)(row0+lm)*K + k0 + lk4];
        As[lk4+0][lm]=a.x; As[lk4+1][lm]=a.y; As[lk4+2][lm]=a.z; As[lk4+3][lm]=a.w;
        *(float4*)&Bs[lbk][lbn] = *(const float4*)&Bm[(size_t)(k0+lbk)*Ncols + col0 + lbn];
        __syncthreads();
        #pragma unroll
        for (int k=0;k<16;k++){
            float av[4], bv[4];
            *(float4*)av = *(const float4*)&As[k][ty*4];
            *(float4*)bv = *(const float4*)&Bs[k][tx*4];
            #pragma unroll
            for (int m=0;m<4;m++)
                #pragma unroll
                for (int n=0;n<4;n++) acc[m][n] = fmaf(av[m], bv[n], acc[m][n]);
        }
        __syncthreads();
    }
    #pragma unroll
    for (int m=0;m<4;m++){
        const int row = row0 + ty*4 + m;
        #pragma unroll
        for (int n=0;n<4;n++){
            const int col = col0 + tx*4 + n;
            float v = acc[m][n] + bias[col];
            if (GELU) v = gelu_f(v);
            C[(size_t)row*ldc + col] = v;
        }
    }
}

// ---------------- fused relational flash attention ----------------
// grid (N/64, H, B), 256 threads. 64 queries x 64 keys per tile, online softmax,
// per-(i,j) relation gather of V from a 64x4x32 smem tile.
__global__ void __launch_bounds__(256) attn_kernel(
    const float* __restrict__ Q, const float* __restrict__ Kb,
    const float* __restrict__ V, const int* __restrict__ adj,
    float* __restrict__ O)
{
    extern __shared__ float sm[];
    float* Qst  = sm;                  // [32][64]  2048
    float* Kst  = Qst + 2048;          // [32][64]  2048
    float* Ss   = Kst + 2048;          // [64][64]  4096
    float* Vs   = Ss  + 4096;          // [64*4][32] 8192
    int*   adjS = (int*)(Vs + 8192);   // [64][64]  4096 ints
    float* mrow = (float*)(adjS + 4096);
    float* lrow = mrow + 64;
    float* crow = lrow + 64;

    const int t  = threadIdx.x;
    const int it = blockIdx.x, h = blockIdx.y, b = blockIdx.z;
    const int i0 = it*64;
    const int lr = t>>2, lc = (t&3)*8;

    // Q tile -> transposed smem [k][i]
    {
        const float* p = Q + (size_t)(b*N_ + i0 + lr)*D_ + h*DH_ + lc;
        float4 a0 = *(const float4*)p;
        float4 a1 = *(const float4*)(p+4);
        Qst[(lc+0)*64+lr]=a0.x; Qst[(lc+1)*64+lr]=a0.y;
        Qst[(lc+2)*64+lr]=a0.z; Qst[(lc+3)*64+lr]=a0.w;
        Qst[(lc+4)*64+lr]=a1.x; Qst[(lc+5)*64+lr]=a1.y;
        Qst[(lc+6)*64+lr]=a1.z; Qst[(lc+7)*64+lr]=a1.w;
    }
    if (t < 64){ mrow[t] = -1e30f; lrow[t] = 0.f; }
    float o[8] = {0,0,0,0,0,0,0,0};
    const int orow = t>>2, od = (t&3)*8;
    __syncthreads();

    for (int jt = 0; jt < 16; jt++){
        const int j0 = jt*64;
        // K tile -> transposed smem
        {
            const float* p = Kb + (size_t)(b*N_ + j0 + lr)*D_ + h*DH_ + lc;
            float4 a0 = *(const float4*)p;
            float4 a1 = *(const float4*)(p+4);
            Kst[(lc+0)*64+lr]=a0.x; Kst[(lc+1)*64+lr]=a0.y;
            Kst[(lc+2)*64+lr]=a0.z; Kst[(lc+3)*64+lr]=a0.w;
            Kst[(lc+4)*64+lr]=a1.x; Kst[(lc+5)*64+lr]=a1.y;
            Kst[(lc+6)*64+lr]=a1.z; Kst[(lc+7)*64+lr]=a1.w;
        }
        // adj tile (int32)
        {
            const int i = t>>2, jc = (t&3)*16;
            const int4* ap = (const int4*)(adj + (size_t)(b*N_ + i0 + i)*N_ + j0 + jc);
            int4 x0=ap[0], x1=ap[1], x2=ap[2], x3=ap[3];
            *(int4*)&adjS[i*64+jc+ 0]=x0; *(int4*)&adjS[i*64+jc+ 4]=x1;
            *(int4*)&adjS[i*64+jc+ 8]=x2; *(int4*)&adjS[i*64+jc+12]=x3;
        }
        // V tile: 64 keys x 4 relations x 32 dims
        #pragma unroll
        for (int ii=0; ii<8; ii++){
            int id = t + 256*ii;
            int f = id & 7, vr = id >> 3;      // vr = j*4 + r
            int j = vr >> 2, rr = vr & 3;
            float4 v = *(const float4*)&V[(size_t)(b*N_ + j0 + j)*(R_*D_) + rr*D_ + h*DH_ + f*4];
            *(float4*)&Vs[vr*32 + f*4] = v;
        }
        __syncthreads();

        // S = Q @ K^T * scale
        {
            const int tx = t & 15, ty = t >> 4;
            float acc[4][4] = {};
            #pragma unroll
            for (int k=0;k<32;k++){
                float qa[4], kv[4];
                *(float4*)qa = *(const float4*)&Qst[k*64 + ty*4];
                *(float4*)kv = *(const float4*)&Kst[k*64 + tx*4];
                #pragma unroll
                for (int m=0;m<4;m++)
                    #pragma unroll
                    for (int n=0;n<4;n++) acc[m][n] = fmaf(qa[m], kv[n], acc[m][n]);
            }
            const float scale = 0.17677669529663688f;  // 1/sqrt(32)
            #pragma unroll
            for (int m=0;m<4;m++){
                float4 v;
                v.x=acc[m][0]*scale; v.y=acc[m][1]*scale;
                v.z=acc[m][2]*scale; v.w=acc[m][3]*scale;
                *(float4*)&Ss[(ty*4+m)*64 + tx*4] = v;
            }
        }
        __syncthreads();

        // online softmax (4 threads per row)
        {
            const int row = t>>2, g = t&3;
            float mx = -1e30f;
            #pragma unroll
            for (int jj=0;jj<16;jj++) mx = fmaxf(mx, Ss[row*64 + g + jj*4]);
            mx = fmaxf(mx, __shfl_xor_sync(0xffffffffu, mx, 1));
            mx = fmaxf(mx, __shfl_xor_sync(0xffffffffu, mx, 2));
            float mold = mrow[row];
            float mnew = fmaxf(mold, mx);
            float s = 0.f;
            #pragma unroll
            for (int jj=0;jj<16;jj++){
                int idx = row*64 + g + jj*4;
                float p = __expf(Ss[idx] - mnew);
                Ss[idx] = p; s += p;
            }
            s += __shfl_xor_sync(0xffffffffu, s, 1);
            s += __shfl_xor_sync(0xffffffffu, s, 2);
            if (g == 0){
                float c = __expf(mold - mnew);
                mrow[row] = mnew;
                lrow[row] = lrow[row]*c + s;
                crow[row] = c;
            }
        }
        __syncthreads();

        // PV with relation gather
        {
            float c = crow[orow];
            #pragma unroll
            for (int q=0;q<8;q++) o[q] *= c;
            #pragma unroll 4
            for (int jj=0;jj<64;jj++){
                float p = Ss[orow*64 + jj];
                int rr = adjS[orow*64 + jj];
                if (rr < 4){
                    const float* vp = &Vs[(jj*4+rr)*32 + od];
                    float4 v0 = *(const float4*)vp;
                    float4 v1 = *(const float4*)(vp+4);
                    o[0]=fmaf(p,v0.x,o[0]); o[1]=fmaf(p,v0.y,o[1]);
                    o[2]=fmaf(p,v0.z,o[2]); o[3]=fmaf(p,v0.w,o[3]);
                    o[4]=fmaf(p,v1.x,o[4]); o[5]=fmaf(p,v1.y,o[5]);
                    o[6]=fmaf(p,v1.z,o[6]); o[7]=fmaf(p,v1.w,o[7]);
                }
            }
        }
        __syncthreads();
    }

    const float linv = 1.f / lrow[orow];
    float* op = O + (size_t)(b*N_ + i0 + orow)*D_ + h*DH_ + od;
    float4 r0, r1;
    r0.x=o[0]*linv; r0.y=o[1]*linv; r0.z=o[2]*linv; r0.w=o[3]*linv;
    r1.x=o[4]*linv; r1.y=o[5]*linv; r1.z=o[6]*linv; r1.w=o[7]*linv;
    *(float4*)op = r0; *(float4*)(op+4) = r1;
}

// ---------------- residual + LayerNorm: out = LN(X + Y) * g + beta ----------------
__global__ void __launch_bounds__(256) ln_kernel(
    const float* __restrict__ X, const float* __restrict__ Y,
    const float* __restrict__ g, const float* __restrict__ beta,
    float* __restrict__ out)
{
    __shared__ float red[8];
    const int row = blockIdx.x, t = threadIdx.x;
    float v = X[(size_t)row*D_ + t] + Y[(size_t)row*D_ + t];

    float s = v;
    #pragma unroll
    for (int off=16; off>0; off>>=1) s += __shfl_xor_sync(0xffffffffu, s, off);
    if ((t&31)==0) red[t>>5] = s;
    __syncthreads();
    if (t < 8){
        float x = red[t];
        x += __shfl_xor_sync(0xffu, x, 1);
        x += __shfl_xor_sync(0xffu, x, 2);
        x += __shfl_xor_sync(0xffu, x, 4);
        if (t==0) red[0] = x;
    }
    __syncthreads();
    const float mean = red[0] * (1.0f/D_);
    __syncthreads();

    const float d = v - mean;
    float s2 = d*d;
    #pragma unroll
    for (int off=16; off>0; off>>=1) s2 += __shfl_xor_sync(0xffffffffu, s2, off);
    if ((t&31)==0) red[t>>5] = s2;
    __syncthreads();
    if (t < 8){
        float x = red[t];
        x += __shfl_xor_sync(0xffu, x, 1);
        x += __shfl_xor_sync(0xffu, x, 2);
        x += __shfl_xor_sync(0xffu, x, 4);
        if (t==0) red[0] = x;
    }
    __syncthreads();
    const float var = red[0] * (1.0f/D_);
    const float rstd = rsqrtf(var + 1e-5f);
    out[(size_t)row*D_ + t] = d*rstd*g[t] + beta[t];
}

// ---------------- launch ----------------
extern "C" void kernel_launch(void* const* d_in, const int* in_sizes, int n_in,
                              void* d_out, int out_size)
{
    const float* src = (const float*)d_in[0];
    const int*   adj = (const int*)  d_in[1];
    const float* Wq  = (const float*)d_in[2];  const float* bq  = (const float*)d_in[3];
    const float* Wk  = (const float*)d_in[4];  const float* bk  = (const float*)d_in[5];
    const float* Wv  = (const float*)d_in[6];  const float* bv  = (const float*)d_in[7];
    const float* Wo  = (const float*)d_in[8];  const float* bo  = (const float*)d_in[9];
    const float* W1  = (const float*)d_in[10]; const float* b1  = (const float*)d_in[11];
    const float* W2  = (const float*)d_in[12]; const float* b2  = (const float*)d_in[13];
    const float* g1  = (const float*)d_in[14]; const float* be1 = (const float*)d_in[15];
    const float* g2  = (const float*)d_in[16]; const float* be2 = (const float*)d_in[17];
    float* out = (float*)d_out;

    void* p;
    cudaGetSymbolAddress(&p, g_Q);  float* Qb  = (float*)p;
    cudaGetSymbolAddress(&p, g_K);  float* Kb2 = (float*)p;
    cudaGetSymbolAddress(&p, g_V);  float* Vb  = (float*)p;
    cudaGetSymbolAddress(&p, g_O);  float* Ob  = (float*)p;
    cudaGetSymbolAddress(&p, g_T1); float* T1  = (float*)p;
    cudaGetSymbolAddress(&p, g_X);  float* Xb  = (float*)p;
    cudaGetSymbolAddress(&p, g_F1); float* F1  = (float*)p;
    cudaGetSymbolAddress(&p, g_T2); float* T2  = (float*)p;

    const dim3 blk(256);
    const dim3 gProj(D_/64, M_/64);

    // Q, K, V0..V3 projections
    gemm_kernel<false><<<gProj, blk>>>(src, Wq, bq, Qb,  D_, D_, D_);
    gemm_kernel<false><<<gProj, blk>>>(src, Wk, bk, Kb2, D_, D_, D_);
    for (int r = 0; r < R_; r++)
        gemm_kernel<false><<<gProj, blk>>>(src, Wv + (size_t)r*D_*D_, bv + r*D_,
                                           Vb + r*D_, D_, D_, R_*D_);

    // fused relational flash attention
    const int smemA = (2048+2048+4096+8192+4096)*4 + 3*64*4;   // 82688 B
    cudaFuncSetAttribute(attn_kernel, cudaFuncAttributeMaxDynamicSharedMemorySize, smemA);
    attn_kernel<<<dim3(N_/64, H_, B_), blk, smemA>>>(Qb, Kb2, Vb, adj, Ob);

    // output projection + residual LN1
    gemm_kernel<false><<<gProj, blk>>>(Ob, Wo, bo, T1, D_, D_, D_);
    ln_kernel<<<M_, 256>>>(src, T1, g1, be1, Xb);

    // FFN
    gemm_kernel<true ><<<dim3(FF_/64, M_/64), blk>>>(Xb, W1, b1, F1, FF_, D_, FF_);
    gemm_kernel<false><<<gProj, blk>>>(F1, W2, b2, T2, D_, FF_, D_);
    ln_kernel<<<M_, 256>>>(Xb, T2, g2, be2, out);
}

// round 4
// speedup vs baseline: 1.1165x; 1.1165x over previous
#include <cuda_runtime.h>
#include <mma.h>
#include <math.h>

using namespace nvcuda;

#define B_  8
#define N_  1024
#define D_  256
#define H_  8
#define DH_ 32
#define R_  4
#define FF_ 1024
#define M_  (B_*N_)   // 8192 rows

// ---- scratch (device globals: no allocations allowed) ----
__device__ float g_Q[M_*D_];
__device__ float g_K[M_*D_];
__device__ float g_V[(size_t)M_*R_*D_];   // [b*N+n][r*256 + c]
__device__ float g_O[M_*D_];
__device__ float g_T1[M_*D_];
__device__ float g_X[M_*D_];
__device__ float g_F1[(size_t)M_*FF_];
__device__ float g_T2[M_*D_];

__device__ __forceinline__ float gelu_f(float x){
    return 0.5f*x*(1.0f + erff(x*0.70710678118654752440f));
}

// =================== TF32 wmma GEMM: C = A(MxK)@B(KxN) + bias, opt GELU ===================
// BM=128, BN=64, BK=32, 256 threads (8 warps, 4x2), warp tile 32x32 (2x2 m16n16k8 frags).
template<bool GELU>
__global__ void __launch_bounds__(256) gemm_tc(
    const float* __restrict__ A, const float* __restrict__ Bm,
    const float* __restrict__ bias, float* __restrict__ C,
    int Ncols, int K, int ldc)
{
    __shared__ float sm[9216];            // union: load bufs (7424) / epilogue Cs 128x72 (9216)
    float* As = sm;                       // [128][40]
    float* Bs = sm + 5120;                // [32][72]
    float* Cs = sm;                       // [128][72]

    const int t = threadIdx.x;
    const int w = t >> 5;
    const int wr = w >> 1, wc = w & 1;
    const int row0 = blockIdx.y*128, col0 = blockIdx.x*64;

    const int rowA = t >> 1, cA = (t & 1)*16;   // A: 2 thr/row, 16 floats each
    const int rowB = t >> 3, cB = (t & 7)*8;    // B: 8 thr/row, 8 floats each

    wmma::fragment<wmma::accumulator,16,16,8,float> acc[2][2];
    #pragma unroll
    for (int i=0;i<2;i++)
        #pragma unroll
        for (int j=0;j<2;j++) wmma::fill_fragment(acc[i][j], 0.f);

    float4 pa[4], pb[2];
    {
        const float* ap = &A[(size_t)(row0+rowA)*K + cA];
        #pragma unroll
        for (int i=0;i<4;i++) pa[i] = *(const float4*)(ap + 4*i);
        const float* bp = &Bm[(size_t)rowB*Ncols + col0 + cB];
        #pragma unroll
        for (int i=0;i<2;i++) pb[i] = *(const float4*)(bp + 4*i);
    }

    for (int k0 = 0; k0 < K; k0 += 32){
        __syncthreads();
        #pragma unroll
        for (int i=0;i<4;i++) *(float4*)&As[rowA*40 + cA + 4*i] = pa[i];
        #pragma unroll
        for (int i=0;i<2;i++) *(float4*)&Bs[rowB*72 + cB + 4*i] = pb[i];
        __syncthreads();

        if (k0 + 32 < K){
            const float* ap = &A[(size_t)(row0+rowA)*K + k0 + 32 + cA];
            #pragma unroll
            for (int i=0;i<4;i++) pa[i] = *(const float4*)(ap + 4*i);
            const float* bp = &Bm[(size_t)(k0+32+rowB)*Ncols + col0 + cB];
            #pragma unroll
            for (int i=0;i<2;i++) pb[i] = *(const float4*)(bp + 4*i);
        }

        #pragma unroll
        for (int kk=0; kk<4; kk++){
            const int k8 = kk*8;
            wmma::fragment<wmma::matrix_a,16,16,8,wmma::precision::tf32,wmma::row_major> fa[2];
            wmma::fragment<wmma::matrix_b,16,16,8,wmma::precision::tf32,wmma::row_major> fb[2];
            #pragma unroll
            for (int i=0;i<2;i++){
                wmma::load_matrix_sync(fa[i], &As[(wr*32 + i*16)*40 + k8], 40);
                #pragma unroll
                for (int e=0;e<fa[i].num_elements;e++) fa[i].x[e] = wmma::__float_to_tf32(fa[i].x[e]);
            }
            #pragma unroll
            for (int j=0;j<2;j++){
                wmma::load_matrix_sync(fb[j], &Bs[k8*72 + wc*32 + j*16], 72);
                #pragma unroll
                for (int e=0;e<fb[j].num_elements;e++) fb[j].x[e] = wmma::__float_to_tf32(fb[j].x[e]);
            }
            #pragma unroll
            for (int i=0;i<2;i++)
                #pragma unroll
                for (int j=0;j<2;j++) wmma::mma_sync(acc[i][j], fa[i], fb[j], acc[i][j]);
        }
    }

    __syncthreads();
    #pragma unroll
    for (int i=0;i<2;i++)
        #pragma unroll
        for (int j=0;j<2;j++)
            wmma::store_matrix_sync(&Cs[(wr*32+i*16)*72 + wc*32 + j*16], acc[i][j], 72, wmma::mem_row_major);
    __syncthreads();

    {
        const int row = t >> 1, c0 = (t & 1)*32;
        #pragma unroll
        for (int i=0;i<8;i++){
            float4 v = *(const float4*)&Cs[row*72 + c0 + i*4];
            const int cg = col0 + c0 + i*4;
            v.x += bias[cg+0]; v.y += bias[cg+1]; v.z += bias[cg+2]; v.w += bias[cg+3];
            if (GELU){ v.x=gelu_f(v.x); v.y=gelu_f(v.y); v.z=gelu_f(v.z); v.w=gelu_f(v.w); }
            *(float4*)&C[(size_t)(row0+row)*ldc + cg] = v;
        }
    }
}

// =================== fused relational flash attention (TF32 wmma) ===================
// grid (N/64, H, B), 256 thr. 64q x 64k tiles. Scores via wmma; PV via masked dense MMA:
// out = sum_r (P .* (adj==r)) @ V_r, with online-softmax rescale of an fp32 register O.
#define Q0  0
#define K0  2560
#define S0  5120
#define P0  9728
#define V0  14336
#define O0  24576
#define MR0 27136
#define LR0 27200
#define CR0 27264
#define FLTS 27328
#define ADJ0 (FLTS*4)              // byte offset of adjS (uint8 [64][64])
#define SMEM_ATTN (ADJ0 + 4096)    // 113408 B

__global__ void __launch_bounds__(256) attn_tc(
    const float* __restrict__ Q, const float* __restrict__ Kb,
    const float* __restrict__ V, const int* __restrict__ adj,
    float* __restrict__ O)
{
    extern __shared__ float smf[];
    unsigned char* adjS = (unsigned char*)smf + ADJ0;

    const int t = threadIdx.x;
    const int w = t >> 5;
    const int it = blockIdx.x, h = blockIdx.y, b = blockIdx.z;
    const int i0 = it*64;

    // ---- load Q tile (scaled) into Qs[64][40] ----
    {
        const int row = t >> 2, col = ((t*2) & 7)*4;   // 2 float4 per thread
        const float* p = Q + (size_t)(b*N_ + i0 + row)*D_ + h*DH_ + col;
        float4 a0 = *(const float4*)p;
        float4 a1 = *(const float4*)(p+4);
        const float sc = 0.17677669529663688f; // 1/sqrt(32)
        a0.x*=sc; a0.y*=sc; a0.z*=sc; a0.w*=sc;
        a1.x*=sc; a1.y*=sc; a1.z*=sc; a1.w*=sc;
        *(float4*)&smf[Q0 + row*40 + col]     = a0;
        *(float4*)&smf[Q0 + row*40 + col + 4] = a1;
    }
    if (t < 64){ smf[MR0+t] = -1e30f; smf[LR0+t] = 0.f; }
    float o[8] = {0,0,0,0,0,0,0,0};
    const int orow = t>>2, od = (t&3)*8;
    __syncthreads();

    for (int jt = 0; jt < 16; jt++){
        const int j0 = jt*64;
        // K tile -> Ks[64][40]
        {
            const int row = t >> 2, col = ((t*2) & 7)*4;
            const float* p = Kb + (size_t)(b*N_ + j0 + row)*D_ + h*DH_ + col;
            *(float4*)&smf[K0 + row*40 + col]     = *(const float4*)p;
            *(float4*)&smf[K0 + row*40 + col + 4] = *(const float4*)(p+4);
        }
        // adj tile -> bytes
        {
            const int i = t>>2, jc = (t&3)*16;
            const int4* ap = (const int4*)(adj + (size_t)(b*N_ + i0 + i)*N_ + j0 + jc);
            unsigned int pk[4];
            #pragma unroll
            for (int q=0;q<4;q++){
                int4 x = ap[q];
                pk[q] = (unsigned)x.x | ((unsigned)x.y<<8) | ((unsigned)x.z<<16) | ((unsigned)x.w<<24);
            }
            *(uint4*)&adjS[i*64 + jc] = *(uint4*)pk;
        }
        // V tiles: Vs[r][64][40]
        #pragma unroll
        for (int ii=0; ii<8; ii++){
            const int id = t + 256*ii;             // 0..2047 float4 slots
            const int jr = id >> 3, f = id & 7;    // jr: r*64+j
            const int r = jr >> 6, j = jr & 63;
            float4 v = *(const float4*)&V[(size_t)(b*N_ + j0 + j)*(R_*D_) + r*D_ + h*DH_ + f*4];
            *(float4*)&smf[V0 + r*2560 + j*40 + f*4] = v;
        }
        __syncthreads();

        // ---- scores: S = Qs @ Ks^T (wmma, 16 tiles of 16x16, 2 per warp) ----
        #pragma unroll
        for (int tn=0; tn<2; tn++){
            const int tt = w*2 + tn;
            const int mi = tt >> 2, ni = tt & 3;
            wmma::fragment<wmma::accumulator,16,16,8,float> sa;
            wmma::fill_fragment(sa, 0.f);
            #pragma unroll
            for (int kk=0; kk<4; kk++){
                wmma::fragment<wmma::matrix_a,16,16,8,wmma::precision::tf32,wmma::row_major> fa;
                wmma::fragment<wmma::matrix_b,16,16,8,wmma::precision::tf32,wmma::col_major> fb;
                wmma::load_matrix_sync(fa, &smf[Q0 + (mi*16)*40 + kk*8], 40);
                wmma::load_matrix_sync(fb, &smf[K0 + (ni*16)*40 + kk*8], 40);
                #pragma unroll
                for (int e=0;e<fa.num_elements;e++) fa.x[e] = wmma::__float_to_tf32(fa.x[e]);
                #pragma unroll
                for (int e=0;e<fb.num_elements;e++) fb.x[e] = wmma::__float_to_tf32(fb.x[e]);
                wmma::mma_sync(sa, fa, fb, sa);
            }
            wmma::store_matrix_sync(&smf[S0 + (mi*16)*72 + ni*16], sa, 72, wmma::mem_row_major);
        }
        __syncthreads();

        // ---- online softmax (4 threads per row) ----
        {
            const int row = t>>2, g = t&3;
            float mx = -1e30f;
            #pragma unroll
            for (int jj=0;jj<16;jj++) mx = fmaxf(mx, smf[S0 + row*72 + g + jj*4]);
            mx = fmaxf(mx, __shfl_xor_sync(0xffffffffu, mx, 1));
            mx = fmaxf(mx, __shfl_xor_sync(0xffffffffu, mx, 2));
            const float mold = smf[MR0+row];
            const float mnew = fmaxf(mold, mx);
            float s = 0.f;
            #pragma unroll
            for (int jj=0;jj<16;jj++){
                const int idx = S0 + row*72 + g + jj*4;
                float p = __expf(smf[idx] - mnew);
                smf[idx] = p; s += p;
            }
            s += __shfl_xor_sync(0xffffffffu, s, 1);
            s += __shfl_xor_sync(0xffffffffu, s, 2);
            if (g == 0){
                const float c = __expf(mold - mnew);
                smf[MR0+row] = mnew;
                smf[LR0+row] = smf[LR0+row]*c + s;
                smf[CR0+row] = c;
            }
        }
        __syncthreads();

        // ---- PV: out_tile += sum_r (P .* (adj==r)) @ V_r  (1 accum tile 16x16 per warp) ----
        {
            const int mi = w >> 1, ni = w & 1;   // out 64x32 = 4x2 tiles
            wmma::fragment<wmma::accumulator,16,16,8,float> oa;
            wmma::fill_fragment(oa, 0.f);
            for (int r = 0; r < R_; r++){
                // build masked P_r in Pm
                {
                    const int i = t>>2, jc = (t&3)*16;
                    #pragma unroll
                    for (int jj=0;jj<16;jj++){
                        const float v = smf[S0 + i*72 + jc + jj];
                        smf[P0 + i*72 + jc + jj] = (adjS[i*64 + jc + jj] == r) ? v : 0.f;
                    }
                }
                __syncthreads();
                #pragma unroll
                for (int kk=0; kk<8; kk++){
                    wmma::fragment<wmma::matrix_a,16,16,8,wmma::precision::tf32,wmma::row_major> fa;
                    wmma::fragment<wmma::matrix_b,16,16,8,wmma::precision::tf32,wmma::row_major> fb;
                    wmma::load_matrix_sync(fa, &smf[P0 + (mi*16)*72 + kk*8], 72);
                    wmma::load_matrix_sync(fb, &smf[V0 + r*2560 + (kk*8)*40 + ni*16], 40);
                    #pragma unroll
                    for (int e=0;e<fa.num_elements;e++) fa.x[e] = wmma::__float_to_tf32(fa.x[e]);
                    #pragma unroll
                    for (int e=0;e<fb.num_elements;e++) fb.x[e] = wmma::__float_to_tf32(fb.x[e]);
                    wmma::mma_sync(oa, fa, fb, oa);
                }
                __syncthreads();
            }
            wmma::store_matrix_sync(&smf[O0 + (mi*16)*40 + ni*16], oa, 40, wmma::mem_row_major);
        }
        __syncthreads();

        // rescale + accumulate into registers
        {
            const float c = smf[CR0+orow];
            float4 v0 = *(const float4*)&smf[O0 + orow*40 + od];
            float4 v1 = *(const float4*)&smf[O0 + orow*40 + od + 4];
            o[0]=o[0]*c+v0.x; o[1]=o[1]*c+v0.y; o[2]=o[2]*c+v0.z; o[3]=o[3]*c+v0.w;
            o[4]=o[4]*c+v1.x; o[5]=o[5]*c+v1.y; o[6]=o[6]*c+v1.z; o[7]=o[7]*c+v1.w;
        }
        __syncthreads();
    }

    const float linv = 1.f / smf[LR0+orow];
    float* op = O + (size_t)(b*N_ + i0 + orow)*D_ + h*DH_ + od;
    float4 r0, r1;
    r0.x=o[0]*linv; r0.y=o[1]*linv; r0.z=o[2]*linv; r0.w=o[3]*linv;
    r1.x=o[4]*linv; r1.y=o[5]*linv; r1.z=o[6]*linv; r1.w=o[7]*linv;
    *(float4*)op = r0; *(float4*)(op+4) = r1;
}

// =================== residual + LayerNorm ===================
__global__ void __launch_bounds__(256) ln_kernel(
    const float* __restrict__ X, const float* __restrict__ Y,
    const float* __restrict__ g, const float* __restrict__ beta,
    float* __restrict__ out)
{
    __shared__ float red[8];
    const int row = blockIdx.x, t = threadIdx.x;
    float v = X[(size_t)row*D_ + t] + Y[(size_t)row*D_ + t];

    float s = v;
    #pragma unroll
    for (int off=16; off>0; off>>=1) s += __shfl_xor_sync(0xffffffffu, s, off);
    if ((t&31)==0) red[t>>5] = s;
    __syncthreads();
    if (t < 8){
        float x = red[t];
        x += __shfl_xor_sync(0xffu, x, 1);
        x += __shfl_xor_sync(0xffu, x, 2);
        x += __shfl_xor_sync(0xffu, x, 4);
        if (t==0) red[0] = x;
    }
    __syncthreads();
    const float mean = red[0] * (1.0f/D_);
    __syncthreads();

    const float d = v - mean;
    float s2 = d*d;
    #pragma unroll
    for (int off=16; off>0; off>>=1) s2 += __shfl_xor_sync(0xffffffffu, s2, off);
    if ((t&31)==0) red[t>>5] = s2;
    __syncthreads();
    if (t < 8){
        float x = red[t];
        x += __shfl_xor_sync(0xffu, x, 1);
        x += __shfl_xor_sync(0xffu, x, 2);
        x += __shfl_xor_sync(0xffu, x, 4);
        if (t==0) red[0] = x;
    }
    __syncthreads();
    const float var = red[0] * (1.0f/D_);
    const float rstd = rsqrtf(var + 1e-5f);
    out[(size_t)row*D_ + t] = d*rstd*g[t] + beta[t];
}

// =================== launch ===================
extern "C" void kernel_launch(void* const* d_in, const int* in_sizes, int n_in,
                              void* d_out, int out_size)
{
    const float* src = (const float*)d_in[0];
    const int*   adj = (const int*)  d_in[1];
    const float* Wq  = (const float*)d_in[2];  const float* bq  = (const float*)d_in[3];
    const float* Wk  = (const float*)d_in[4];  const float* bk  = (const float*)d_in[5];
    const float* Wv  = (const float*)d_in[6];  const float* bv  = (const float*)d_in[7];
    const float* Wo  = (const float*)d_in[8];  const float* bo  = (const float*)d_in[9];
    const float* W1  = (const float*)d_in[10]; const float* b1  = (const float*)d_in[11];
    const float* W2  = (const float*)d_in[12]; const float* b2  = (const float*)d_in[13];
    const float* g1  = (const float*)d_in[14]; const float* be1 = (const float*)d_in[15];
    const float* g2  = (const float*)d_in[16]; const float* be2 = (const float*)d_in[17];
    float* out = (float*)d_out;

    void* p;
    cudaGetSymbolAddress(&p, g_Q);  float* Qb  = (float*)p;
    cudaGetSymbolAddress(&p, g_K);  float* Kb2 = (float*)p;
    cudaGetSymbolAddress(&p, g_V);  float* Vb  = (float*)p;
    cudaGetSymbolAddress(&p, g_O);  float* Ob  = (float*)p;
    cudaGetSymbolAddress(&p, g_T1); float* T1  = (float*)p;
    cudaGetSymbolAddress(&p, g_X);  float* Xb  = (float*)p;
    cudaGetSymbolAddress(&p, g_F1); float* F1  = (float*)p;
    cudaGetSymbolAddress(&p, g_T2); float* T2  = (float*)p;

    const dim3 blk(256);
    const dim3 gProj(D_/64, M_/128);

    gemm_tc<false><<<gProj, blk>>>(src, Wq, bq, Qb,  D_, D_, D_);
    gemm_tc<false><<<gProj, blk>>>(src, Wk, bk, Kb2, D_, D_, D_);
    for (int r = 0; r < R_; r++)
        gemm_tc<false><<<gProj, blk>>>(src, Wv + (size_t)r*D_*D_, bv + r*D_,
                                       Vb + r*D_, D_, D_, R_*D_);

    cudaFuncSetAttribute(attn_tc, cudaFuncAttributeMaxDynamicSharedMemorySize, SMEM_ATTN);
    attn_tc<<<dim3(N_/64, H_, B_), blk, SMEM_ATTN>>>(Qb, Kb2, Vb, adj, Ob);

    gemm_tc<false><<<gProj, blk>>>(Ob, Wo, bo, T1, D_, D_, D_);
    ln_kernel<<<M_, 256>>>(src, T1, g1, be1, Xb);

    gemm_tc<true ><<<dim3(FF_/64, M_/128), blk>>>(Xb, W1, b1, F1, FF_, D_, FF_);
    gemm_tc<false><<<gProj, blk>>>(F1, W2, b2, T2, D_, FF_, D_);
    ln_kernel<<<M_, 256>>>(Xb, T2, g2, be2, out);
}

// round 5
// speedup vs baseline: 1.4879x; 1.3326x over previous
#include <cuda_runtime.h>
#include <mma.h>
#include <math.h>

using namespace nvcuda;

#define B_  8
#define N_  1024
#define D_  256
#define H_  8
#define DH_ 32
#define R_  4
#define FF_ 1024
#define M_  (B_*N_)   // 8192 rows

// ---- scratch (device globals) ----
__device__ float g_Q[M_*D_];
__device__ float g_K[M_*D_];
__device__ float g_V[(size_t)M_*R_*D_];   // [b*N+n][r*256 + c]
__device__ float g_O[M_*D_];
__device__ float g_T1[M_*D_];
__device__ float g_X[M_*D_];
__device__ float g_F1[(size_t)M_*FF_];
__device__ float g_T2[M_*D_];

__device__ __forceinline__ float gelu_f(float x){
    return 0.5f*x*(1.0f + erff(x*0.70710678118654752440f));
}

// =================== TF32 wmma GEMM core ===================
// BM=128, BN=64, BK=32, 256 threads (8 warps, 4x2), warp tile 32x32.
template<bool GELU>
__device__ __forceinline__ void gemm_body(
    const float* __restrict__ A, const float* __restrict__ Bm,
    const float* __restrict__ bias, float* __restrict__ C,
    int Ncols, int K, int ldc, int bx, int by)
{
    __shared__ float sm[9216];            // union: load bufs (7424) / epilogue Cs 128x72
    float* As = sm;                       // [128][40]
    float* Bs = sm + 5120;                // [32][72]
    float* Cs = sm;                       // [128][72]

    const int t = threadIdx.x;
    const int w = t >> 5;
    const int wr = w >> 1, wc = w & 1;
    const int row0 = by*128, col0 = bx*64;

    const int rowA = t >> 1, cA = (t & 1)*16;
    const int rowB = t >> 3, cB = (t & 7)*8;

    wmma::fragment<wmma::accumulator,16,16,8,float> acc[2][2];
    #pragma unroll
    for (int i=0;i<2;i++)
        #pragma unroll
        for (int j=0;j<2;j++) wmma::fill_fragment(acc[i][j], 0.f);

    float4 pa[4], pb[2];
    {
        const float* ap = &A[(size_t)(row0+rowA)*K + cA];
        #pragma unroll
        for (int i=0;i<4;i++) pa[i] = *(const float4*)(ap + 4*i);
        const float* bp = &Bm[(size_t)rowB*Ncols + col0 + cB];
        #pragma unroll
        for (int i=0;i<2;i++) pb[i] = *(const float4*)(bp + 4*i);
    }

    for (int k0 = 0; k0 < K; k0 += 32){
        __syncthreads();
        #pragma unroll
        for (int i=0;i<4;i++) *(float4*)&As[rowA*40 + cA + 4*i] = pa[i];
        #pragma unroll
        for (int i=0;i<2;i++) *(float4*)&Bs[rowB*72 + cB + 4*i] = pb[i];
        __syncthreads();

        if (k0 + 32 < K){
            const float* ap = &A[(size_t)(row0+rowA)*K + k0 + 32 + cA];
            #pragma unroll
            for (int i=0;i<4;i++) pa[i] = *(const float4*)(ap + 4*i);
            const float* bp = &Bm[(size_t)(k0+32+rowB)*Ncols + col0 + cB];
            #pragma unroll
            for (int i=0;i<2;i++) pb[i] = *(const float4*)(bp + 4*i);
        }

        #pragma unroll
        for (int kk=0; kk<4; kk++){
            const int k8 = kk*8;
            wmma::fragment<wmma::matrix_a,16,16,8,wmma::precision::tf32,wmma::row_major> fa[2];
            wmma::fragment<wmma::matrix_b,16,16,8,wmma::precision::tf32,wmma::row_major> fb[2];
            #pragma unroll
            for (int i=0;i<2;i++){
                wmma::load_matrix_sync(fa[i], &As[(wr*32 + i*16)*40 + k8], 40);
                #pragma unroll
                for (int e=0;e<fa[i].num_elements;e++) fa[i].x[e] = wmma::__float_to_tf32(fa[i].x[e]);
            }
            #pragma unroll
            for (int j=0;j<2;j++){
                wmma::load_matrix_sync(fb[j], &Bs[k8*72 + wc*32 + j*16], 72);
                #pragma unroll
                for (int e=0;e<fb[j].num_elements;e++) fb[j].x[e] = wmma::__float_to_tf32(fb[j].x[e]);
            }
            #pragma unroll
            for (int i=0;i<2;i++)
                #pragma unroll
                for (int j=0;j<2;j++) wmma::mma_sync(acc[i][j], fa[i], fb[j], acc[i][j]);
        }
    }

    __syncthreads();
    #pragma unroll
    for (int i=0;i<2;i++)
        #pragma unroll
        for (int j=0;j<2;j++)
            wmma::store_matrix_sync(&Cs[(wr*32+i*16)*72 + wc*32 + j*16], acc[i][j], 72, wmma::mem_row_major);
    __syncthreads();

    {
        const int row = t >> 1, c0 = (t & 1)*32;
        #pragma unroll
        for (int i=0;i<8;i++){
            float4 v = *(const float4*)&Cs[row*72 + c0 + i*4];
            const int cg = col0 + c0 + i*4;
            v.x += bias[cg+0]; v.y += bias[cg+1]; v.z += bias[cg+2]; v.w += bias[cg+3];
            if (GELU){ v.x=gelu_f(v.x); v.y=gelu_f(v.y); v.z=gelu_f(v.z); v.w=gelu_f(v.w); }
            *(float4*)&C[(size_t)(row0+row)*ldc + cg] = v;
        }
    }
}

template<bool GELU>
__global__ void __launch_bounds__(256) gemm_tc(
    const float* __restrict__ A, const float* __restrict__ Bm,
    const float* __restrict__ bias, float* __restrict__ C,
    int Ncols, int K, int ldc)
{
    gemm_body<GELU>(A, Bm, bias, C, Ncols, K, ldc, blockIdx.x, blockIdx.y);
}

// batched QKV projections: z selects which of 6 GEMMs
struct QKVParams {
    const float* W[6];
    const float* bias[6];
    float*       C[6];
    int          ldc[6];
};

__global__ void __launch_bounds__(256) gemm_qkv(
    const float* __restrict__ A, QKVParams p)
{
    const int z = blockIdx.z;
    gemm_body<false>(A, p.W[z], p.bias[z], p.C[z], D_, D_, p.ldc[z],
                     blockIdx.x, blockIdx.y);
}

// =================== fused relational flash attention (TF32 wmma) ===================
// grid (N/64, H, B), 256 thr, 2 CTAs/SM. 64q x 64k tiles; scores via wmma; PV as
// sum_r (P .* (adj==r)) @ V_r with per-r masked-P staging and one 16x16 out tile/warp.
#define Q0  0                        // [64][36]
#define K0  2304                     // [64][36]
#define V0  4608                     // [4][64][36]
#define S0  13824                    // [64][68]
#define P0  18176                    // [64][68]
#define O0  22528                    // [64][36]
#define MR0 24832
#define LR0 24896
#define CR0 24960
#define FLTS 25024
#define ADJ0 (FLTS*4)                // uint8 [64][64]
#define SMEM_ATTN (ADJ0 + 4096)      // 104192 B -> 2 CTA/SM

__global__ void __launch_bounds__(256) attn_tc(
    const float* __restrict__ Q, const float* __restrict__ Kb,
    const float* __restrict__ V, const int* __restrict__ adj,
    float* __restrict__ O)
{
    extern __shared__ float smf[];
    unsigned char* adjS = (unsigned char*)smf + ADJ0;

    const int t = threadIdx.x;
    const int w = t >> 5;
    const int it = blockIdx.x, h = blockIdx.y, b = blockIdx.z;
    const int i0 = it*64;

    const int lrow = t >> 2, lcol = (t & 3)*8;   // tile loads: 4 thr/row, 8 floats each

    // ---- Q tile (pre-scaled) -> Qs[64][36] ----
    {
        const float* p = Q + (size_t)(b*N_ + i0 + lrow)*D_ + h*DH_ + lcol;
        float4 a0 = *(const float4*)p;
        float4 a1 = *(const float4*)(p+4);
        const float sc = 0.17677669529663688f;   // 1/sqrt(32)
        a0.x*=sc; a0.y*=sc; a0.z*=sc; a0.w*=sc;
        a1.x*=sc; a1.y*=sc; a1.z*=sc; a1.w*=sc;
        *(float4*)&smf[Q0 + lrow*36 + lcol]     = a0;
        *(float4*)&smf[Q0 + lrow*36 + lcol + 4] = a1;
    }
    if (t < 64){ smf[MR0+t] = -1e30f; smf[LR0+t] = 0.f; }
    float o[8] = {0,0,0,0,0,0,0,0};
    const int orow = t>>2, od = (t&3)*8;
    __syncthreads();

    for (int jt = 0; jt < 16; jt++){
        const int j0 = jt*64;
        // K tile
        {
            const float* p = Kb + (size_t)(b*N_ + j0 + lrow)*D_ + h*DH_ + lcol;
            *(float4*)&smf[K0 + lrow*36 + lcol]     = *(const float4*)p;
            *(float4*)&smf[K0 + lrow*36 + lcol + 4] = *(const float4*)(p+4);
        }
        // adj tile -> bytes
        {
            const int i = t>>2, jc = (t&3)*16;
            const int4* ap = (const int4*)(adj + (size_t)(b*N_ + i0 + i)*N_ + j0 + jc);
            unsigned int pk[4];
            #pragma unroll
            for (int q=0;q<4;q++){
                int4 x = ap[q];
                pk[q] = (unsigned)x.x | ((unsigned)x.y<<8) | ((unsigned)x.z<<16) | ((unsigned)x.w<<24);
            }
            *(uint4*)&adjS[i*64 + jc] = *(uint4*)pk;
        }
        // V tiles (all 4 relations): Vs[r][64][36]
        #pragma unroll
        for (int ii=0; ii<8; ii++){
            const int id = t + 256*ii;             // float4 slot 0..2047
            const int jr = id >> 3, f = id & 7;
            const int r = jr >> 6, j = jr & 63;
            float4 v = *(const float4*)&V[(size_t)(b*N_ + j0 + j)*(R_*D_) + r*D_ + h*DH_ + f*4];
            *(float4*)&smf[V0 + r*2304 + j*36 + f*4] = v;
        }
        __syncthreads();

        // ---- scores: S = Qs @ Ks^T, 16 tiles 16x16, 2/warp ----
        #pragma unroll
        for (int tn=0; tn<2; tn++){
            const int tt = w*2 + tn;
            const int mi = tt >> 2, ni = tt & 3;
            wmma::fragment<wmma::accumulator,16,16,8,float> sa;
            wmma::fill_fragment(sa, 0.f);
            #pragma unroll
            for (int kk=0; kk<4; kk++){
                wmma::fragment<wmma::matrix_a,16,16,8,wmma::precision::tf32,wmma::row_major> fa;
                wmma::fragment<wmma::matrix_b,16,16,8,wmma::precision::tf32,wmma::col_major> fb;
                wmma::load_matrix_sync(fa, &smf[Q0 + (mi*16)*36 + kk*8], 36);
                wmma::load_matrix_sync(fb, &smf[K0 + (ni*16)*36 + kk*8], 36);
                #pragma unroll
                for (int e=0;e<fa.num_elements;e++) fa.x[e] = wmma::__float_to_tf32(fa.x[e]);
                #pragma unroll
                for (int e=0;e<fb.num_elements;e++) fb.x[e] = wmma::__float_to_tf32(fb.x[e]);
                wmma::mma_sync(sa, fa, fb, sa);
            }
            wmma::store_matrix_sync(&smf[S0 + (mi*16)*68 + ni*16], sa, 68, wmma::mem_row_major);
        }
        __syncthreads();

        // ---- online softmax (4 thr/row) ----
        {
            const int row = t>>2, g = t&3;
            float mx = -1e30f;
            #pragma unroll
            for (int jj=0;jj<16;jj++) mx = fmaxf(mx, smf[S0 + row*68 + g + jj*4]);
            mx = fmaxf(mx, __shfl_xor_sync(0xffffffffu, mx, 1));
            mx = fmaxf(mx, __shfl_xor_sync(0xffffffffu, mx, 2));
            const float mold = smf[MR0+row];
            const float mnew = fmaxf(mold, mx);
            float s = 0.f;
            #pragma unroll
            for (int jj=0;jj<16;jj++){
                const int idx = S0 + row*68 + g + jj*4;
                float p = __expf(smf[idx] - mnew);
                smf[idx] = p; s += p;
            }
            s += __shfl_xor_sync(0xffffffffu, s, 1);
            s += __shfl_xor_sync(0xffffffffu, s, 2);
            if (g == 0){
                const float c = __expf(mold - mnew);
                smf[MR0+row] = mnew;
                smf[LR0+row] = smf[LR0+row]*c + s;
                smf[CR0+row] = c;
            }
        }
        __syncthreads();

        // ---- PV: out += sum_r (P .* (adj==r)) @ V_r ----
        {
            const int mi = w >> 1, ni = w & 1;     // 64x32 out = 4x2 tiles, 1/warp
            wmma::fragment<wmma::accumulator,16,16,8,float> oa;
            wmma::fill_fragment(oa, 0.f);
            const int bi = t>>2, bjc = (t&3)*16;
            #pragma unroll
            for (int r = 0; r < R_; r++){
                // vectorized masked-P build
                #pragma unroll
                for (int q=0;q<4;q++){
                    const int col = bjc + q*4;
                    float4 sv = *(const float4*)&smf[S0 + bi*68 + col];
                    uchar4 av = *(const uchar4*)&adjS[bi*64 + col];
                    float4 pv;
                    pv.x = (av.x == r) ? sv.x : 0.f;
                    pv.y = (av.y == r) ? sv.y : 0.f;
                    pv.z = (av.z == r) ? sv.z : 0.f;
                    pv.w = (av.w == r) ? sv.w : 0.f;
                    *(float4*)&smf[P0 + bi*68 + col] = pv;
                }
                __syncthreads();
                #pragma unroll
                for (int kk=0; kk<8; kk++){
                    wmma::fragment<wmma::matrix_a,16,16,8,wmma::precision::tf32,wmma::row_major> fa;
                    wmma::fragment<wmma::matrix_b,16,16,8,wmma::precision::tf32,wmma::row_major> fb;
                    wmma::load_matrix_sync(fa, &smf[P0 + (mi*16)*68 + kk*8], 68);
                    wmma::load_matrix_sync(fb, &smf[V0 + r*2304 + (kk*8)*36 + ni*16], 36);
                    #pragma unroll
                    for (int e=0;e<fa.num_elements;e++) fa.x[e] = wmma::__float_to_tf32(fa.x[e]);
                    #pragma unroll
                    for (int e=0;e<fb.num_elements;e++) fb.x[e] = wmma::__float_to_tf32(fb.x[e]);
                    wmma::mma_sync(oa, fa, fb, oa);
                }
                __syncthreads();
            }
            wmma::store_matrix_sync(&smf[O0 + (mi*16)*36 + ni*16], oa, 36, wmma::mem_row_major);
        }
        __syncthreads();

        // rescale + accumulate
        {
            const float c = smf[CR0+orow];
            float4 v0 = *(const float4*)&smf[O0 + orow*36 + od];
            float4 v1 = *(const float4*)&smf[O0 + orow*36 + od + 4];
            o[0]=o[0]*c+v0.x; o[1]=o[1]*c+v0.y; o[2]=o[2]*c+v0.z; o[3]=o[3]*c+v0.w;
            o[4]=o[4]*c+v1.x; o[5]=o[5]*c+v1.y; o[6]=o[6]*c+v1.z; o[7]=o[7]*c+v1.w;
        }
        __syncthreads();
    }

    const float linv = 1.f / smf[LR0+orow];
    float* op = O + (size_t)(b*N_ + i0 + orow)*D_ + h*DH_ + od;
    float4 r0, r1;
    r0.x=o[0]*linv; r0.y=o[1]*linv; r0.z=o[2]*linv; r0.w=o[3]*linv;
    r1.x=o[4]*linv; r1.y=o[5]*linv; r1.z=o[6]*linv; r1.w=o[7]*linv;
    *(float4*)op = r0; *(float4*)(op+4) = r1;
}

// =================== residual + LayerNorm ===================
__global__ void __launch_bounds__(256) ln_kernel(
    const float* __restrict__ X, const float* __restrict__ Y,
    const float* __restrict__ g, const float* __restrict__ beta,
    float* __restrict__ out)
{
    __shared__ float red[8];
    const int row = blockIdx.x, t = threadIdx.x;
    float v = X[(size_t)row*D_ + t] + Y[(size_t)row*D_ + t];

    float s = v;
    #pragma unroll
    for (int off=16; off>0; off>>=1) s += __shfl_xor_sync(0xffffffffu, s, off);
    if ((t&31)==0) red[t>>5] = s;
    __syncthreads();
    if (t < 8){
        float x = red[t];
        x += __shfl_xor_sync(0xffu, x, 1);
        x += __shfl_xor_sync(0xffu, x, 2);
        x += __shfl_xor_sync(0xffu, x, 4);
        if (t==0) red[0] = x;
    }
    __syncthreads();
    const float mean = red[0] * (1.0f/D_);
    __syncthreads();

    const float d = v - mean;
    float s2 = d*d;
    #pragma unroll
    for (int off=16; off>0; off>>=1) s2 += __shfl_xor_sync(0xffffffffu, s2, off);
    if ((t&31)==0) red[t>>5] = s2;
    __syncthreads();
    if (t < 8){
        float x = red[t];
        x += __shfl_xor_sync(0xffu, x, 1);
        x += __shfl_xor_sync(0xffu, x, 2);
        x += __shfl_xor_sync(0xffu, x, 4);
        if (t==0) red[0] = x;
    }
    __syncthreads();
    const float var = red[0] * (1.0f/D_);
    const float rstd = rsqrtf(var + 1e-5f);
    out[(size_t)row*D_ + t] = d*rstd*g[t] + beta[t];
}

// =================== launch ===================
extern "C" void kernel_launch(void* const* d_in, const int* in_sizes, int n_in,
                              void* d_out, int out_size)
{
    const float* src = (const float*)d_in[0];
    const int*   adj = (const int*)  d_in[1];
    const float* Wq  = (const float*)d_in[2];  const float* bq  = (const float*)d_in[3];
    const float* Wk  = (const float*)d_in[4];  const float* bk  = (const float*)d_in[5];
    const float* Wv  = (const float*)d_in[6];  const float* bv  = (const float*)d_in[7];
    const float* Wo  = (const float*)d_in[8];  const float* bo  = (const float*)d_in[9];
    const float* W1  = (const float*)d_in[10]; const float* b1  = (const float*)d_in[11];
    const float* W2  = (const float*)d_in[12]; const float* b2  = (const float*)d_in[13];
    const float* g1  = (const float*)d_in[14]; const float* be1 = (const float*)d_in[15];
    const float* g2  = (const float*)d_in[16]; const float* be2 = (const float*)d_in[17];
    float* out = (float*)d_out;

    void* p;
    cudaGetSymbolAddress(&p, g_Q);  float* Qb  = (float*)p;
    cudaGetSymbolAddress(&p, g_K);  float* Kb2 = (float*)p;
    cudaGetSymbolAddress(&p, g_V);  float* Vb  = (float*)p;
    cudaGetSymbolAddress(&p, g_O);  float* Ob  = (float*)p;
    cudaGetSymbolAddress(&p, g_T1); float* T1  = (float*)p;
    cudaGetSymbolAddress(&p, g_X);  float* Xb  = (float*)p;
    cudaGetSymbolAddress(&p, g_F1); float* F1  = (float*)p;
    cudaGetSymbolAddress(&p, g_T2); float* T2  = (float*)p;

    const dim3 blk(256);

    // --- batched Q/K/V0..V3 projections: one launch, 1536 CTAs ---
    QKVParams qp;
    qp.W[0]=Wq; qp.bias[0]=bq; qp.C[0]=Qb;  qp.ldc[0]=D_;
    qp.W[1]=Wk; qp.bias[1]=bk; qp.C[1]=Kb2; qp.ldc[1]=D_;
    for (int r=0;r<R_;r++){
        qp.W[2+r]=Wv + (size_t)r*D_*D_; qp.bias[2+r]=bv + r*D_;
        qp.C[2+r]=Vb + r*D_; qp.ldc[2+r]=R_*D_;
    }
    gemm_qkv<<<dim3(D_/64, M_/128, 6), blk>>>(src, qp);

    // --- fused relational flash attention ---
    cudaFuncSetAttribute(attn_tc, cudaFuncAttributeMaxDynamicSharedMemorySize, SMEM_ATTN);
    attn_tc<<<dim3(N_/64, H_, B_), blk, SMEM_ATTN>>>(Qb, Kb2, Vb, adj, Ob);

    // --- output projection + LN1 ---
    gemm_tc<false><<<dim3(D_/64, M_/128), blk>>>(Ob, Wo, bo, T1, D_, D_, D_);
    ln_kernel<<<M_, 256>>>(src, T1, g1, be1, Xb);

    // --- FFN + LN2 ---
    gemm_tc<true ><<<dim3(FF_/64, M_/128), blk>>>(Xb, W1, b1, F1, FF_, D_, FF_);
    gemm_tc<false><<<dim3(D_/64, M_/128), blk>>>(F1, W2, b2, T2, D_, FF_, D_);
    ln_kernel<<<M_, 256>>>(Xb, T2, g2, be2, out);
}

// round 6
// speedup vs baseline: 3.1276x; 2.1020x over previous
#include <cuda_runtime.h>
#include <cuda_fp16.h>
#include <mma.h>
#include <math.h>

using namespace nvcuda;

#define B_  8
#define N_  1024
#define D_  256
#define H_  8
#define DH_ 32
#define R_  4
#define FF_ 1024
#define M_  (B_*N_)   // 8192 rows

// ---- scratch (device globals) ----
__device__ float g_Q[M_*D_];
__device__ float g_K[M_*D_];
__device__ float g_V[(size_t)M_*R_*D_];   // [b*N+n][r*256 + c]
__device__ float g_O[M_*D_];
__device__ float g_T1[M_*D_];
__device__ float g_X[M_*D_];
__device__ float g_F1[(size_t)M_*FF_];
__device__ float g_T2[M_*D_];

__device__ __forceinline__ float gelu_f(float x){
    return 0.5f*x*(1.0f + erff(x*0.70710678118654752440f));
}
__device__ __forceinline__ uint2 f4_to_h4(float4 v){
    __half2 lo = __floats2half2_rn(v.x, v.y);
    __half2 hi = __floats2half2_rn(v.z, v.w);
    uint2 r; r.x = *(unsigned*)&lo; r.y = *(unsigned*)&hi; return r;
}

// =================== fp16 wmma GEMM core ===================
// BM=128, BN=64, BK=32, 256 threads (8 warps, 4x2), warp tile 32x32, fp32 accum.
template<bool GELU>
__device__ __forceinline__ void gemm_body(
    const float* __restrict__ A, const float* __restrict__ Bm,
    const float* __restrict__ bias, float* __restrict__ C,
    int Ncols, int K, int ldc, int bx, int by)
{
    __shared__ float sm[9216];                 // 36864 B: half tiles (14848 B) / epilogue Cs
    __half* As = (__half*)sm;                  // [128][40] halves
    __half* Bs = (__half*)sm + 5120;           // [32][72] halves
    float*  Cs = sm;                           // [128][72] floats

    const int t = threadIdx.x;
    const int w = t >> 5;
    const int wr = w >> 1, wc = w & 1;
    const int row0 = by*128, col0 = bx*64;

    const int rowA = t >> 1, cA = (t & 1)*16;
    const int rowB = t >> 3, cB = (t & 7)*8;

    wmma::fragment<wmma::accumulator,16,16,16,float> acc[2][2];
    #pragma unroll
    for (int i=0;i<2;i++)
        #pragma unroll
        for (int j=0;j<2;j++) wmma::fill_fragment(acc[i][j], 0.f);

    float4 pa[4], pb[2];
    {
        const float* ap = &A[(size_t)(row0+rowA)*K + cA];
        #pragma unroll
        for (int i=0;i<4;i++) pa[i] = *(const float4*)(ap + 4*i);
        const float* bp = &Bm[(size_t)rowB*Ncols + col0 + cB];
        #pragma unroll
        for (int i=0;i<2;i++) pb[i] = *(const float4*)(bp + 4*i);
    }

    for (int k0 = 0; k0 < K; k0 += 32){
        __syncthreads();
        {
            uint4 h0, h1;
            uint2 a0=f4_to_h4(pa[0]), a1=f4_to_h4(pa[1]), a2=f4_to_h4(pa[2]), a3=f4_to_h4(pa[3]);
            h0.x=a0.x; h0.y=a0.y; h0.z=a1.x; h0.w=a1.y;
            h1.x=a2.x; h1.y=a2.y; h1.z=a3.x; h1.w=a3.y;
            *(uint4*)&As[rowA*40 + cA]     = h0;
            *(uint4*)&As[rowA*40 + cA + 8] = h1;
            uint2 b0=f4_to_h4(pb[0]), b1=f4_to_h4(pb[1]);
            uint4 hb; hb.x=b0.x; hb.y=b0.y; hb.z=b1.x; hb.w=b1.y;
            *(uint4*)&Bs[rowB*72 + cB] = hb;
        }
        __syncthreads();

        if (k0 + 32 < K){
            const float* ap = &A[(size_t)(row0+rowA)*K + k0 + 32 + cA];
            #pragma unroll
            for (int i=0;i<4;i++) pa[i] = *(const float4*)(ap + 4*i);
            const float* bp = &Bm[(size_t)(k0+32+rowB)*Ncols + col0 + cB];
            #pragma unroll
            for (int i=0;i<2;i++) pb[i] = *(const float4*)(bp + 4*i);
        }

        #pragma unroll
        for (int kk=0; kk<2; kk++){
            const int k16 = kk*16;
            wmma::fragment<wmma::matrix_a,16,16,16,__half,wmma::row_major> fa[2];
            wmma::fragment<wmma::matrix_b,16,16,16,__half,wmma::row_major> fb[2];
            #pragma unroll
            for (int i=0;i<2;i++)
                wmma::load_matrix_sync(fa[i], &As[(wr*32 + i*16)*40 + k16], 40);
            #pragma unroll
            for (int j=0;j<2;j++)
                wmma::load_matrix_sync(fb[j], &Bs[k16*72 + wc*32 + j*16], 72);
            #pragma unroll
            for (int i=0;i<2;i++)
                #pragma unroll
                for (int j=0;j<2;j++) wmma::mma_sync(acc[i][j], fa[i], fb[j], acc[i][j]);
        }
    }

    __syncthreads();
    #pragma unroll
    for (int i=0;i<2;i++)
        #pragma unroll
        for (int j=0;j<2;j++)
            wmma::store_matrix_sync(&Cs[(wr*32+i*16)*72 + wc*32 + j*16], acc[i][j], 72, wmma::mem_row_major);
    __syncthreads();

    {
        const int row = t >> 1, c0 = (t & 1)*32;
        #pragma unroll
        for (int i=0;i<8;i++){
            float4 v = *(const float4*)&Cs[row*72 + c0 + i*4];
            const int cg = col0 + c0 + i*4;
            v.x += bias[cg+0]; v.y += bias[cg+1]; v.z += bias[cg+2]; v.w += bias[cg+3];
            if (GELU){ v.x=gelu_f(v.x); v.y=gelu_f(v.y); v.z=gelu_f(v.z); v.w=gelu_f(v.w); }
            *(float4*)&C[(size_t)(row0+row)*ldc + cg] = v;
        }
    }
}

template<bool GELU>
__global__ void __launch_bounds__(256) gemm_tc(
    const float* __restrict__ A, const float* __restrict__ Bm,
    const float* __restrict__ bias, float* __restrict__ C,
    int Ncols, int K, int ldc)
{
    gemm_body<GELU>(A, Bm, bias, C, Ncols, K, ldc, blockIdx.x, blockIdx.y);
}

struct QKVParams {
    const float* W[6];
    const float* bias[6];
    float*       C[6];
    int          ldc[6];
};

__global__ void __launch_bounds__(256) gemm_qkv(
    const float* __restrict__ A, QKVParams p)
{
    const int z = blockIdx.z;
    gemm_body<false>(A, p.W[z], p.bias[z], p.C[z], D_, D_, p.ldc[z],
                     blockIdx.x, blockIdx.y);
}

// =================== fused relational flash attention (fp16 wmma) ===================
// grid (N/64, H, B), 256 thr, 2 CTA/SM. PV as single concat GEMM:
// [P0|P1|P2|P3](64x256) @ [V0;V1;V2;V3](256x32), fp32 accum, online softmax.
// byte offsets in dynamic smem:
#define QH0  0                       // half [64][40]   5120
#define KH0  5120                    // half [64][40]   5120
#define VH0  10240                   // half [256][40]  20480  (row = r*64+j)
#define PH0  30720                   // half [64][272]  34816  (col = r*64+j)
#define SF0  65536                   // float [64][68]  17408
#define OF0  82944                   // float [64][36]  9216
#define MR0  92160                   // float[64]
#define LR0  92416
#define CR0  92672
#define ADJ0 92928                   // uint8 [64][64]  4096
#define SMEM_ATTN 97024

__global__ void __launch_bounds__(256) attn_tc(
    const float* __restrict__ Q, const float* __restrict__ Kb,
    const float* __restrict__ V, const int* __restrict__ adj,
    float* __restrict__ O)
{
    extern __shared__ char smb[];
    __half* Qh = (__half*)(smb + QH0);
    __half* Kh = (__half*)(smb + KH0);
    __half* Vh = (__half*)(smb + VH0);
    __half* Ph = (__half*)(smb + PH0);
    float*  Sf = (float*)(smb + SF0);
    float*  Of = (float*)(smb + OF0);
    float*  mrow = (float*)(smb + MR0);
    float*  lrow = (float*)(smb + LR0);
    float*  crow = (float*)(smb + CR0);
    unsigned char* adjS = (unsigned char*)(smb + ADJ0);

    const int t = threadIdx.x;
    const int w = t >> 5;
    const int it = blockIdx.x, h = blockIdx.y, b = blockIdx.z;
    const int i0 = it*64;

    const int lrowi = t >> 2, lcol = (t & 3)*8;

    // ---- Q tile (pre-scaled) -> half ----
    {
        const float* p = Q + (size_t)(b*N_ + i0 + lrowi)*D_ + h*DH_ + lcol;
        float4 a0 = *(const float4*)p;
        float4 a1 = *(const float4*)(p+4);
        const float sc = 0.17677669529663688f;   // 1/sqrt(32)
        a0.x*=sc; a0.y*=sc; a0.z*=sc; a0.w*=sc;
        a1.x*=sc; a1.y*=sc; a1.z*=sc; a1.w*=sc;
        uint2 h0 = f4_to_h4(a0), h1 = f4_to_h4(a1);
        uint4 hv; hv.x=h0.x; hv.y=h0.y; hv.z=h1.x; hv.w=h1.y;
        *(uint4*)&Qh[lrowi*40 + lcol] = hv;
    }
    if (t < 64){ mrow[t] = -1e30f; lrow[t] = 0.f; }
    float o[8] = {0,0,0,0,0,0,0,0};
    const int orow = t>>2, od = (t&3)*8;
    __syncthreads();

    for (int jt = 0; jt < 16; jt++){
        const int j0 = jt*64;
        // K tile
        {
            const float* p = Kb + (size_t)(b*N_ + j0 + lrowi)*D_ + h*DH_ + lcol;
            float4 a0 = *(const float4*)p;
            float4 a1 = *(const float4*)(p+4);
            uint2 h0 = f4_to_h4(a0), h1 = f4_to_h4(a1);
            uint4 hv; hv.x=h0.x; hv.y=h0.y; hv.z=h1.x; hv.w=h1.y;
            *(uint4*)&Kh[lrowi*40 + lcol] = hv;
        }
        // adj tile -> bytes
        {
            const int i = t>>2, jc = (t&3)*16;
            const int4* ap = (const int4*)(adj + (size_t)(b*N_ + i0 + i)*N_ + j0 + jc);
            unsigned int pk[4];
            #pragma unroll
            for (int q=0;q<4;q++){
                int4 x = ap[q];
                pk[q] = (unsigned)x.x | ((unsigned)x.y<<8) | ((unsigned)x.z<<16) | ((unsigned)x.w<<24);
            }
            *(uint4*)&adjS[i*64 + jc] = *(uint4*)pk;
        }
        // V tiles: Vh[(r*64+j)][40]
        #pragma unroll
        for (int ii=0; ii<8; ii++){
            const int id = t + 256*ii;             // float4 slot 0..2047
            const int jr = id >> 3, f = id & 7;    // jr = r*64+j
            const int r = jr >> 6, j = jr & 63;
            float4 v = *(const float4*)&V[(size_t)(b*N_ + j0 + j)*(R_*D_) + r*D_ + h*DH_ + f*4];
            *(uint2*)&Vh[jr*40 + f*4] = f4_to_h4(v);
        }
        __syncthreads();

        // ---- scores: S = Qh @ Kh^T (16 tiles 16x16, 2/warp, k16 x2) ----
        #pragma unroll
        for (int tn=0; tn<2; tn++){
            const int tt = w*2 + tn;
            const int mi = tt >> 2, ni = tt & 3;
            wmma::fragment<wmma::accumulator,16,16,16,float> sa;
            wmma::fill_fragment(sa, 0.f);
            #pragma unroll
            for (int kk=0; kk<2; kk++){
                wmma::fragment<wmma::matrix_a,16,16,16,__half,wmma::row_major> fa;
                wmma::fragment<wmma::matrix_b,16,16,16,__half,wmma::col_major> fb;
                wmma::load_matrix_sync(fa, &Qh[(mi*16)*40 + kk*16], 40);
                wmma::load_matrix_sync(fb, &Kh[(ni*16)*40 + kk*16], 40);
                wmma::mma_sync(sa, fa, fb, sa);
            }
            wmma::store_matrix_sync(&Sf[(mi*16)*68 + ni*16], sa, 68, wmma::mem_row_major);
        }
        __syncthreads();

        // ---- online softmax (4 thr/row) ----
        {
            const int row = t>>2, g = t&3;
            float mx = -1e30f;
            #pragma unroll
            for (int jj=0;jj<16;jj++) mx = fmaxf(mx, Sf[row*68 + g + jj*4]);
            mx = fmaxf(mx, __shfl_xor_sync(0xffffffffu, mx, 1));
            mx = fmaxf(mx, __shfl_xor_sync(0xffffffffu, mx, 2));
            const float mold = mrow[row];
            const float mnew = fmaxf(mold, mx);
            float s = 0.f;
            #pragma unroll
            for (int jj=0;jj<16;jj++){
                const int idx = row*68 + g + jj*4;
                float p = __expf(Sf[idx] - mnew);
                Sf[idx] = p; s += p;
            }
            s += __shfl_xor_sync(0xffffffffu, s, 1);
            s += __shfl_xor_sync(0xffffffffu, s, 2);
            if (g == 0){
                const float c = __expf(mold - mnew);
                mrow[row] = mnew;
                lrow[row] = lrow[row]*c + s;
                crow[row] = c;
            }
        }
        __syncthreads();

        // ---- build concat masked P (half): Ph[i][r*64 + j] ----
        {
            const int bi = t>>2, bjc = (t&3)*16;
            float sv[16]; unsigned char av[16];
            #pragma unroll
            for (int q=0;q<4;q++){
                *(float4*)&sv[q*4] = *(const float4*)&Sf[bi*68 + bjc + q*4];
                *(uchar4*)&av[q*4] = *(const uchar4*)&adjS[bi*64 + bjc + q*4];
            }
            #pragma unroll
            for (int r=0;r<R_;r++){
                __half hp[16];
                #pragma unroll
                for (int jj=0;jj<16;jj++)
                    hp[jj] = __float2half((av[jj]==r) ? sv[jj] : 0.f);
                *(uint4*)&Ph[bi*272 + r*64 + bjc]     = *(uint4*)&hp[0];
                *(uint4*)&Ph[bi*272 + r*64 + bjc + 8] = *(uint4*)&hp[8];
            }
        }
        __syncthreads();

        // ---- PV: O64x32 = Ph(64x256) @ Vh(256x32); 8 tiles, 1/warp, k16 x16 ----
        {
            const int mi = w >> 1, ni = w & 1;
            wmma::fragment<wmma::accumulator,16,16,16,float> oa;
            wmma::fill_fragment(oa, 0.f);
            #pragma unroll
            for (int kk=0; kk<16; kk++){
                wmma::fragment<wmma::matrix_a,16,16,16,__half,wmma::row_major> fa;
                wmma::fragment<wmma::matrix_b,16,16,16,__half,wmma::row_major> fb;
                wmma::load_matrix_sync(fa, &Ph[(mi*16)*272 + kk*16], 272);
                wmma::load_matrix_sync(fb, &Vh[(kk*16)*40 + ni*16], 40);
                wmma::mma_sync(oa, fa, fb, oa);
            }
            wmma::store_matrix_sync(&Of[(mi*16)*36 + ni*16], oa, 36, wmma::mem_row_major);
        }
        __syncthreads();

        // rescale + accumulate into registers
        {
            const float c = crow[orow];
            float4 v0 = *(const float4*)&Of[orow*36 + od];
            float4 v1 = *(const float4*)&Of[orow*36 + od + 4];
            o[0]=o[0]*c+v0.x; o[1]=o[1]*c+v0.y; o[2]=o[2]*c+v0.z; o[3]=o[3]*c+v0.w;
            o[4]=o[4]*c+v1.x; o[5]=o[5]*c+v1.y; o[6]=o[6]*c+v1.z; o[7]=o[7]*c+v1.w;
        }
        __syncthreads();
    }

    const float linv = 1.f / lrow[orow];
    float* op = O + (size_t)(b*N_ + i0 + orow)*D_ + h*DH_ + od;
    float4 r0, r1;
    r0.x=o[0]*linv; r0.y=o[1]*linv; r0.z=o[2]*linv; r0.w=o[3]*linv;
    r1.x=o[4]*linv; r1.y=o[5]*linv; r1.z=o[6]*linv; r1.w=o[7]*linv;
    *(float4*)op = r0; *(float4*)(op+4) = r1;
}

// =================== residual + LayerNorm ===================
__global__ void __launch_bounds__(256) ln_kernel(
    const float* __restrict__ X, const float* __restrict__ Y,
    const float* __restrict__ g, const float* __restrict__ beta,
    float* __restrict__ out)
{
    __shared__ float red[8];
    const int row = blockIdx.x, t = threadIdx.x;
    float v = X[(size_t)row*D_ + t] + Y[(size_t)row*D_ + t];

    float s = v;
    #pragma unroll
    for (int off=16; off>0; off>>=1) s += __shfl_xor_sync(0xffffffffu, s, off);
    if ((t&31)==0) red[t>>5] = s;
    __syncthreads();
    if (t < 8){
        float x = red[t];
        x += __shfl_xor_sync(0xffu, x, 1);
        x += __shfl_xor_sync(0xffu, x, 2);
        x += __shfl_xor_sync(0xffu, x, 4);
        if (t==0) red[0] = x;
    }
    __syncthreads();
    const float mean = red[0] * (1.0f/D_);
    __syncthreads();

    const float d = v - mean;
    float s2 = d*d;
    #pragma unroll
    for (int off=16; off>0; off>>=1) s2 += __shfl_xor_sync(0xffffffffu, s2, off);
    if ((t&31)==0) red[t>>5] = s2;
    __syncthreads();
    if (t < 8){
        float x = red[t];
        x += __shfl_xor_sync(0xffu, x, 1);
        x += __shfl_xor_sync(0xffu, x, 2);
        x += __shfl_xor_sync(0xffu, x, 4);
        if (t==0) red[0] = x;
    }
    __syncthreads();
    const float var = red[0] * (1.0f/D_);
    const float rstd = rsqrtf(var + 1e-5f);
    out[(size_t)row*D_ + t] = d*rstd*g[t] + beta[t];
}

// =================== launch ===================
extern "C" void kernel_launch(void* const* d_in, const int* in_sizes, int n_in,
                              void* d_out, int out_size)
{
    const float* src = (const float*)d_in[0];
    const int*   adj = (const int*)  d_in[1];
    const float* Wq  = (const float*)d_in[2];  const float* bq  = (const float*)d_in[3];
    const float* Wk  = (const float*)d_in[4];  const float* bk  = (const float*)d_in[5];
    const float* Wv  = (const float*)d_in[6];  const float* bv  = (const float*)d_in[7];
    const float* Wo  = (const float*)d_in[8];  const float* bo  = (const float*)d_in[9];
    const float* W1  = (const float*)d_in[10]; const float* b1  = (const float*)d_in[11];
    const float* W2  = (const float*)d_in[12]; const float* b2  = (const float*)d_in[13];
    const float* g1  = (const float*)d_in[14]; const float* be1 = (const float*)d_in[15];
    const float* g2  = (const float*)d_in[16]; const float* be2 = (const float*)d_in[17];
    float* out = (float*)d_out;

    void* p;
    cudaGetSymbolAddress(&p, g_Q);  float* Qb  = (float*)p;
    cudaGetSymbolAddress(&p, g_K);  float* Kb2 = (float*)p;
    cudaGetSymbolAddress(&p, g_V);  float* Vb  = (float*)p;
    cudaGetSymbolAddress(&p, g_O);  float* Ob  = (float*)p;
    cudaGetSymbolAddress(&p, g_T1); float* T1  = (float*)p;
    cudaGetSymbolAddress(&p, g_X);  float* Xb  = (float*)p;
    cudaGetSymbolAddress(&p, g_F1); float* F1  = (float*)p;
    cudaGetSymbolAddress(&p, g_T2); float* T2  = (float*)p;

    const dim3 blk(256);

    // --- batched Q/K/V0..V3 projections ---
    QKVParams qp;
    qp.W[0]=Wq; qp.bias[0]=bq; qp.C[0]=Qb;  qp.ldc[0]=D_;
    qp.W[1]=Wk; qp.bias[1]=bk; qp.C[1]=Kb2; qp.ldc[1]=D_;
    for (int r=0;r<R_;r++){
        qp.W[2+r]=Wv + (size_t)r*D_*D_; qp.bias[2+r]=bv + r*D_;
        qp.C[2+r]=Vb + r*D_; qp.ldc[2+r]=R_*D_;
    }
    gemm_qkv<<<dim3(D_/64, M_/128, 6), blk>>>(src, qp);

    // --- fused relational flash attention ---
    cudaFuncSetAttribute(attn_tc, cudaFuncAttributeMaxDynamicSharedMemorySize, SMEM_ATTN);
    attn_tc<<<dim3(N_/64, H_, B_), blk, SMEM_ATTN>>>(Qb, Kb2, Vb, adj, Ob);

    // --- output projection + LN1 ---
    gemm_tc<false><<<dim3(D_/64, M_/128), blk>>>(Ob, Wo, bo, T1, D_, D_, D_);
    ln_kernel<<<M_, 256>>>(src, T1, g1, be1, Xb);

    // --- FFN + LN2 ---
    gemm_tc<true ><<<dim3(FF_/64, M_/128), blk>>>(Xb, W1, b1, F1, FF_, D_, FF_);
    gemm_tc<false><<<dim3(D_/64, M_/128), blk>>>(F1, W2, b2, T2, D_, FF_, D_);
    ln_kernel<<<M_, 256>>>(Xb, T2, g2, be2, out);
}

// round 10
// speedup vs baseline: 4.8694x; 1.5569x over previous
#include <cuda_runtime.h>
#include <cuda_fp16.h>
#include <math.h>

#define B_  8
#define N_  1024
#define D_  256
#define H_  8
#define DH_ 32
#define R_  4
#define FF_ 1024
#define M_  (B_*N_)   // 8192 rows

// ---- scratch (device globals) ----
__device__ __half g_Qh[M_*D_];
__device__ __half g_Kh[M_*D_];
__device__ __half g_Vh[(size_t)M_*R_*D_];     // [n][r*256 + h*32 + d]
__device__ unsigned char g_adjB[(size_t)M_*N_];
__device__ float g_O[M_*D_];
__device__ float g_T1[M_*D_];
__device__ float g_X[M_*D_];
__device__ float g_F1[(size_t)M_*FF_];
__device__ float g_T2[M_*D_];

__device__ __forceinline__ float gelu_f(float x){
    return 0.5f*x*(1.0f + erff(x*0.70710678118654752440f));
}
__device__ __forceinline__ uint2 f4_to_h4(float4 v){
    __half2 lo = __floats2half2_rn(v.x, v.y);
    __half2 hi = __floats2half2_rn(v.z, v.w);
    uint2 r; r.x = *(unsigned*)&lo; r.y = *(unsigned*)&hi; return r;
}

// ---------------- PTX helpers ----------------
__device__ __forceinline__ unsigned sm32(const void* p){
    return (unsigned)__cvta_generic_to_shared(p);
}
__device__ __forceinline__ void cp16(unsigned dst, const void* src){
    asm volatile("cp.async.cg.shared.global [%0], [%1], 16;" :: "r"(dst), "l"(src) : "memory");
}
__device__ __forceinline__ void ldsm4(unsigned* r, unsigned a){
    asm volatile("ldmatrix.sync.aligned.m8n8.x4.shared.b16 {%0,%1,%2,%3}, [%4];"
        : "=r"(r[0]),"=r"(r[1]),"=r"(r[2]),"=r"(r[3]) : "r"(a));
}
__device__ __forceinline__ void ldsm4t(unsigned* r, unsigned a){
    asm volatile("ldmatrix.sync.aligned.m8n8.x4.trans.shared.b16 {%0,%1,%2,%3}, [%4];"
        : "=r"(r[0]),"=r"(r[1]),"=r"(r[2]),"=r"(r[3]) : "r"(a));
}
__device__ __forceinline__ void mma16816(float* c, const unsigned* a, unsigned b0, unsigned b1){
    asm volatile("mma.sync.aligned.m16n8k16.row.col.f32.f16.f16.f32 "
        "{%0,%1,%2,%3}, {%4,%5,%6,%7}, {%8,%9}, {%0,%1,%2,%3};"
        : "+f"(c[0]),"+f"(c[1]),"+f"(c[2]),"+f"(c[3])
        : "r"(a[0]),"r"(a[1]),"r"(a[2]),"r"(a[3]), "r"(b0),"r"(b1));
}

// =================== fp16 mma GEMM (f32 in, f32 or f16 out) ===================
#include <mma.h>
using namespace nvcuda;

template<bool GELU, bool HOUT>
__device__ __forceinline__ void gemm_body(
    const float* __restrict__ A, const float* __restrict__ Bm,
    const float* __restrict__ bias, void* __restrict__ Cout,
    int Ncols, int K, int ldc, float osc, int bx, int by)
{
    __shared__ float sm[9216];
    __half* As = (__half*)sm;                  // [128][40]
    __half* Bs = (__half*)sm + 5120;           // [32][72]
    float*  Cs = sm;                           // [128][72]

    const int t = threadIdx.x;
    const int w = t >> 5;
    const int wr = w >> 1, wc = w & 1;
    const int row0 = by*128, col0 = bx*64;

    const int rowA = t >> 1, cA = (t & 1)*16;
    const int rowB = t >> 3, cB = (t & 7)*8;

    wmma::fragment<wmma::accumulator,16,16,16,float> acc[2][2];
    #pragma unroll
    for (int i=0;i<2;i++)
        #pragma unroll
        for (int j=0;j<2;j++) wmma::fill_fragment(acc[i][j], 0.f);

    float4 pa[4], pb[2];
    {
        const float* ap = &A[(size_t)(row0+rowA)*K + cA];
        #pragma unroll
        for (int i=0;i<4;i++) pa[i] = *(const float4*)(ap + 4*i);
        const float* bp = &Bm[(size_t)rowB*Ncols + col0 + cB];
        #pragma unroll
        for (int i=0;i<2;i++) pb[i] = *(const float4*)(bp + 4*i);
    }

    for (int k0 = 0; k0 < K; k0 += 32){
        __syncthreads();
        {
            uint4 h0, h1;
            uint2 a0=f4_to_h4(pa[0]), a1=f4_to_h4(pa[1]), a2=f4_to_h4(pa[2]), a3=f4_to_h4(pa[3]);
            h0.x=a0.x; h0.y=a0.y; h0.z=a1.x; h0.w=a1.y;
            h1.x=a2.x; h1.y=a2.y; h1.z=a3.x; h1.w=a3.y;
            *(uint4*)&As[rowA*40 + cA]     = h0;
            *(uint4*)&As[rowA*40 + cA + 8] = h1;
            uint2 b0=f4_to_h4(pb[0]), b1=f4_to_h4(pb[1]);
            uint4 hb; hb.x=b0.x; hb.y=b0.y; hb.z=b1.x; hb.w=b1.y;
            *(uint4*)&Bs[rowB*72 + cB] = hb;
        }
        __syncthreads();

        if (k0 + 32 < K){
            const float* ap = &A[(size_t)(row0+rowA)*K + k0 + 32 + cA];
            #pragma unroll
            for (int i=0;i<4;i++) pa[i] = *(const float4*)(ap + 4*i);
            const float* bp = &Bm[(size_t)(k0+32+rowB)*Ncols + col0 + cB];
            #pragma unroll
            for (int i=0;i<2;i++) pb[i] = *(const float4*)(bp + 4*i);
        }

        #pragma unroll
        for (int kk=0; kk<2; kk++){
            const int k16 = kk*16;
            wmma::fragment<wmma::matrix_a,16,16,16,__half,wmma::row_major> fa[2];
            wmma::fragment<wmma::matrix_b,16,16,16,__half,wmma::row_major> fb[2];
            #pragma unroll
            for (int i=0;i<2;i++)
                wmma::load_matrix_sync(fa[i], &As[(wr*32 + i*16)*40 + k16], 40);
            #pragma unroll
            for (int j=0;j<2;j++)
                wmma::load_matrix_sync(fb[j], &Bs[k16*72 + wc*32 + j*16], 72);
            #pragma unroll
            for (int i=0;i<2;i++)
                #pragma unroll
                for (int j=0;j<2;j++) wmma::mma_sync(acc[i][j], fa[i], fb[j], acc[i][j]);
        }
    }

    __syncthreads();
    #pragma unroll
    for (int i=0;i<2;i++)
        #pragma unroll
        for (int j=0;j<2;j++)
            wmma::store_matrix_sync(&Cs[(wr*32+i*16)*72 + wc*32 + j*16], acc[i][j], 72, wmma::mem_row_major);
    __syncthreads();

    {
        const int row = t >> 1, c0 = (t & 1)*32;
        #pragma unroll
        for (int i=0;i<8;i++){
            float4 v = *(const float4*)&Cs[row*72 + c0 + i*4];
            const int cg = col0 + c0 + i*4;
            v.x += bias[cg+0]; v.y += bias[cg+1]; v.z += bias[cg+2]; v.w += bias[cg+3];
            if (HOUT){ v.x*=osc; v.y*=osc; v.z*=osc; v.w*=osc; }
            if (GELU){ v.x=gelu_f(v.x); v.y=gelu_f(v.y); v.z=gelu_f(v.z); v.w=gelu_f(v.w); }
            if (HOUT){
                __half* Ch = (__half*)Cout;
                uint2 hv = f4_to_h4(v);
                *(uint2*)&Ch[(size_t)(row0+row)*ldc + cg] = hv;
            } else {
                float* Cf = (float*)Cout;
                *(float4*)&Cf[(size_t)(row0+row)*ldc + cg] = v;
            }
        }
    }
}

template<bool GELU>
__global__ void __launch_bounds__(256) gemm_tc(
    const float* __restrict__ A, const float* __restrict__ Bm,
    const float* __restrict__ bias, float* __restrict__ C,
    int Ncols, int K, int ldc)
{
    gemm_body<GELU,false>(A, Bm, bias, C, Ncols, K, ldc, 1.f, blockIdx.x, blockIdx.y);
}

struct QKVParams {
    const float* W[6];
    const float* bias[6];
    __half*      C[6];
    int          ldc[6];
    float        scale[6];
};

__global__ void __launch_bounds__(256) gemm_qkv(
    const float* __restrict__ A, QKVParams p)
{
    const int z = blockIdx.z;
    gemm_body<false,true>(A, p.W[z], p.bias[z], p.C[z], D_, D_, p.ldc[z],
                          p.scale[z], blockIdx.x, blockIdx.y);
}

// adj int32 -> uint8
__global__ void __launch_bounds__(256) adj2byte(
    const int* __restrict__ adj, unsigned char* __restrict__ out)
{
    const size_t i = (size_t)blockIdx.x*256 + threadIdx.x;
    int4 v = ((const int4*)adj)[i];
    uchar4 o;
    o.x=(unsigned char)v.x; o.y=(unsigned char)v.y;
    o.z=(unsigned char)v.z; o.w=(unsigned char)v.w;
    ((uchar4*)out)[i] = o;
}

// =================== relational flash attention: raw mma + cp.async ===================
// grid (16, 8, 8), 256 thr (8 warps: rg=w>>1 row group, jh=w&1 key half).
// smem: 2 x (Kh[64][40] | Vh[256][40] | adj[64][64]) + softmax scratch = 60928 B.
#define BUFB 29696
#define ATTN_SMEM 60928

__device__ __forceinline__ void issue_tile(
    unsigned char* bufp, int t, int b, int h, int i0, int j0,
    const __half* __restrict__ Kg, const __half* __restrict__ Vg,
    const unsigned char* __restrict__ adjB)
{
    const int row = t>>2, seg = t&3;
    cp16(sm32(bufp + row*80 + seg*16),
         Kg + (size_t)(b*N_ + j0 + row)*D_ + h*DH_ + seg*8);
    cp16(sm32(bufp + 25600 + row*64 + seg*16),
         adjB + (size_t)(b*N_ + i0 + row)*N_ + j0 + seg*16);
    #pragma unroll
    for (int k2=0;k2<4;k2++){
        const int c = t + 256*k2;
        const int rj = c>>2, sg = c&3;
        const int r = rj>>6, j = rj&63;
        cp16(sm32(bufp + 5120 + rj*80 + sg*16),
             Vg + (size_t)(b*N_ + j0 + j)*(R_*D_) + r*D_ + h*DH_ + sg*8);
    }
}

__global__ void __launch_bounds__(256, 2) attn_mma(
    const __half* __restrict__ Qg, const __half* __restrict__ Kg,
    const __half* __restrict__ Vg, const unsigned char* __restrict__ adjB,
    float* __restrict__ O)
{
    extern __shared__ unsigned char smn[];
    unsigned char* buf0 = smn;
    unsigned char* buf1 = smn + BUFB;
    float* pmax = (float*)(smn + 2*BUFB);          // [2][64]
    float* psum = (float*)(smn + 2*BUFB + 512);    // [2][64]
    float* mrow = (float*)(smn + 2*BUFB + 1024);   // [64]
    float* lrow = (float*)(smn + 2*BUFB + 1280);   // [64]

    const int t = threadIdx.x, l = t & 31, w = t >> 5;
    const int rg = w >> 1, jh = w & 1;
    const int it = blockIdx.x, h = blockIdx.y, b = blockIdx.z;
    const int i0 = it*64;
    const int r0row = l >> 2, cp2 = (l & 3)*2;
    const int rowg0 = rg*16 + r0row;
    const int grp = l >> 3, li = l & 7;

    // ---- stage Q tile (half, pre-scaled by GEMM) into buf1 head ----
    {
        const int row = t>>2, seg = t&3;
        uint4 qv = *(const uint4*)(Qg + (size_t)(b*N_ + i0 + row)*D_ + h*DH_ + seg*8);
        *(uint4*)(buf1 + row*80 + seg*16) = qv;
    }
    if (t < 64){ mrow[t] = -1e30f; lrow[t] = 0.f; }
    issue_tile(buf0, t, b, h, i0, 0, Kg, Vg, adjB);
    asm volatile("cp.async.commit_group;" ::: "memory");
    __syncthreads();

    // ---- Q fragments (A-operand order: m1=row+8, m2=k+8) ----
    unsigned qf[2][4];
    {
        const int qrow = rg*16 + li + (grp&1)*8;          // FIX: row+8 for lane groups 1,3
        #pragma unroll
        for (int kb=0;kb<2;kb++){
            unsigned a = sm32(buf1 + qrow*80 + (kb*16 + ((grp>>1)&1)*8)*2);  // FIX: k+8 groups 2,3
            ldsm4(qf[kb], a);
        }
    }

    float Od[4][4];
    #pragma unroll
    for (int i=0;i<4;i++){ Od[i][0]=0;Od[i][1]=0;Od[i][2]=0;Od[i][3]=0; }

    for (int jt = 0; jt < 16; jt++){
        unsigned char* bufc = (jt & 1) ? buf1 : buf0;
        unsigned char* bufn = (jt & 1) ? buf0 : buf1;
        __syncthreads();                         // prior compute on bufn done
        if (jt + 1 < 16){
            issue_tile(bufn, t, b, h, i0, (jt+1)*64, Kg, Vg, adjB);
            asm volatile("cp.async.commit_group;" ::: "memory");
            asm volatile("cp.async.wait_group 1;" ::: "memory");
        } else {
            asm volatile("cp.async.wait_group 0;" ::: "memory");
        }
        __syncthreads();                         // tile jt visible

        // ---- K fragments for this warp's j-half (B-operand via non-trans ldsm) ----
        unsigned kf[2][2][4];
        {
            const int krow = jh*32 + li + ((grp>>1)&1)*8;
            #pragma unroll
            for (int kb=0;kb<2;kb++)
                #pragma unroll
                for (int p=0;p<2;p++){
                    unsigned a = sm32(bufc + (krow + p*16)*80 + (kb*16 + (grp&1)*8)*2);
                    ldsm4(kf[kb][p], a);
                }
        }

        // ---- scores: 16x32 per warp, 4 n8 tiles ----
        float sd[4][4];
        #pragma unroll
        for (int t8=0;t8<4;t8++){
            sd[t8][0]=0;sd[t8][1]=0;sd[t8][2]=0;sd[t8][3]=0;
            #pragma unroll
            for (int kb=0;kb<2;kb++){
                const int p = t8>>1, q = (t8&1)*2;
                mma16816(sd[t8], qf[kb], kf[kb][p][q], kf[kb][p][q+1]);
            }
        }

        // ---- online softmax (registers + quad shuffles + smem combine) ----
        float mx0 = -1e30f, mx1 = -1e30f;
        #pragma unroll
        for (int t8=0;t8<4;t8++){
            mx0 = fmaxf(mx0, fmaxf(sd[t8][0], sd[t8][1]));
            mx1 = fmaxf(mx1, fmaxf(sd[t8][2], sd[t8][3]));
        }
        mx0 = fmaxf(mx0, __shfl_xor_sync(0xffffffffu, mx0, 1));
        mx0 = fmaxf(mx0, __shfl_xor_sync(0xffffffffu, mx0, 2));
        mx1 = fmaxf(mx1, __shfl_xor_sync(0xffffffffu, mx1, 1));
        mx1 = fmaxf(mx1, __shfl_xor_sync(0xffffffffu, mx1, 2));
        if ((l&3)==0){
            pmax[jh*64 + rowg0]     = mx0;
            pmax[jh*64 + rowg0 + 8] = mx1;
        }
        __syncthreads();
        const float mold0 = mrow[rowg0], mold1 = mrow[rowg0+8];
        const float mn0 = fmaxf(mold0, fmaxf(pmax[rowg0],   pmax[64+rowg0]));
        const float mn1 = fmaxf(mold1, fmaxf(pmax[rowg0+8], pmax[64+rowg0+8]));
        const float c0 = __expf(mold0 - mn0), c1 = __expf(mold1 - mn1);
        float s0 = 0.f, s1 = 0.f;
        #pragma unroll
        for (int t8=0;t8<4;t8++){
            sd[t8][0] = __expf(sd[t8][0] - mn0);
            sd[t8][1] = __expf(sd[t8][1] - mn0);
            sd[t8][2] = __expf(sd[t8][2] - mn1);
            sd[t8][3] = __expf(sd[t8][3] - mn1);
            s0 += sd[t8][0] + sd[t8][1];
            s1 += sd[t8][2] + sd[t8][3];
        }
        s0 += __shfl_xor_sync(0xffffffffu, s0, 1);
        s0 += __shfl_xor_sync(0xffffffffu, s0, 2);
        s1 += __shfl_xor_sync(0xffffffffu, s1, 1);
        s1 += __shfl_xor_sync(0xffffffffu, s1, 2);
        if ((l&3)==0){
            psum[jh*64 + rowg0]     = s0;
            psum[jh*64 + rowg0 + 8] = s1;
        }
        __syncthreads();
        if (jh==0 && (l&3)==0){
            lrow[rowg0]   = lrow[rowg0]  *c0 + psum[rowg0]   + psum[64+rowg0];
            lrow[rowg0+8] = lrow[rowg0+8]*c1 + psum[rowg0+8] + psum[64+rowg0+8];
            mrow[rowg0]   = mn0;
            mrow[rowg0+8] = mn1;
        }

        // rescale O accumulators
        #pragma unroll
        for (int t8=0;t8<4;t8++){
            Od[t8][0]*=c0; Od[t8][1]*=c0; Od[t8][2]*=c1; Od[t8][3]*=c1;
        }

        // p -> half2 + adj codes
        unsigned h2r[4][2], ax2[4][2];
        const unsigned char* adjT = bufc + 25600;
        #pragma unroll
        for (int t8=0;t8<4;t8++){
            __half2 p01 = __floats2half2_rn(sd[t8][0], sd[t8][1]);
            __half2 p23 = __floats2half2_rn(sd[t8][2], sd[t8][3]);
            h2r[t8][0] = *(unsigned*)&p01;
            h2r[t8][1] = *(unsigned*)&p23;
            const int colo = jh*32 + t8*8 + cp2;
            unsigned a0 = *(const unsigned short*)(adjT + rowg0*64 + colo);
            unsigned a1 = *(const unsigned short*)(adjT + (rowg0+8)*64 + colo);
            ax2[t8][0] = (a0 & 0xffu) | ((a0 & 0xff00u) << 8);
            ax2[t8][1] = (a1 & 0xffu) | ((a1 & 0xff00u) << 8);
        }

        // ---- PV: Od += sum_r (P .* (adj==r)) @ V_r ----
        const unsigned char* Vb = bufc + 5120;
        #pragma unroll
        for (int r=0;r<R_;r++){
            const unsigned rr2 = (unsigned)r * 0x00010001u;
            #pragma unroll
            for (int s=0;s<2;s++){
                unsigned am[4];
                am[0] = h2r[2*s  ][0] & __vcmpeq2(ax2[2*s  ][0], rr2);
                am[1] = h2r[2*s  ][1] & __vcmpeq2(ax2[2*s  ][1], rr2);
                am[2] = h2r[2*s+1][0] & __vcmpeq2(ax2[2*s+1][0], rr2);
                am[3] = h2r[2*s+1][1] & __vcmpeq2(ax2[2*s+1][1], rr2);
                const int kbase = r*64 + jh*32 + s*16;
                const int vrow = kbase + li + (grp&1)*8;
                #pragma unroll
                for (int p=0;p<2;p++){
                    unsigned vb[4];
                    unsigned a = sm32(Vb + vrow*80 + (p*16 + (grp>>1)*8)*2);
                    ldsm4t(vb, a);
                    mma16816(Od[2*p],   am, vb[0], vb[1]);
                    mma16816(Od[2*p+1], am, vb[2], vb[3]);
                }
            }
        }
    }

    // ---- combine jh halves + normalize + store ----
    float* Ost = (float*)buf0;     // [64][34]
    if (jh == 1){
        #pragma unroll
        for (int t8=0;t8<4;t8++){
            *(float2*)&Ost[rowg0*34 + t8*8 + cp2]     = make_float2(Od[t8][0], Od[t8][1]);
            *(float2*)&Ost[(rowg0+8)*34 + t8*8 + cp2] = make_float2(Od[t8][2], Od[t8][3]);
        }
    }
    __syncthreads();
    if (jh == 0){
        const float li0 = 1.f/lrow[rowg0], li1 = 1.f/lrow[rowg0+8];
        #pragma unroll
        for (int t8=0;t8<4;t8++){
            float2 p0 = *(float2*)&Ost[rowg0*34 + t8*8 + cp2];
            float2 p1 = *(float2*)&Ost[(rowg0+8)*34 + t8*8 + cp2];
            float2 o0 = make_float2((Od[t8][0]+p0.x)*li0, (Od[t8][1]+p0.y)*li0);
            float2 o1 = make_float2((Od[t8][2]+p1.x)*li1, (Od[t8][3]+p1.y)*li1);
            *(float2*)&O[(size_t)(b*N_+i0+rowg0)*D_   + h*DH_ + t8*8 + cp2] = o0;
            *(float2*)&O[(size_t)(b*N_+i0+rowg0+8)*D_ + h*DH_ + t8*8 + cp2] = o1;
        }
    }
}

// =================== residual + LayerNorm ===================
__global__ void __launch_bounds__(256) ln_kernel(
    const float* __restrict__ X, const float* __restrict__ Y,
    const float* __restrict__ g, const float* __restrict__ beta,
    float* __restrict__ out)
{
    __shared__ float red[8];
    const int row = blockIdx.x, t = threadIdx.x;
    float v = X[(size_t)row*D_ + t] + Y[(size_t)row*D_ + t];

    float s = v;
    #pragma unroll
    for (int off=16; off>0; off>>=1) s += __shfl_xor_sync(0xffffffffu, s, off);
    if ((t&31)==0) red[t>>5] = s;
    __syncthreads();
    if (t < 8){
        float x = red[t];
        x += __shfl_xor_sync(0xffu, x, 1);
        x += __shfl_xor_sync(0xffu, x, 2);
        x += __shfl_xor_sync(0xffu, x, 4);
        if (t==0) red[0] = x;
    }
    __syncthreads();
    const float mean = red[0] * (1.0f/D_);
    __syncthreads();

    const float d = v - mean;
    float s2 = d*d;
    #pragma unroll
    for (int off=16; off>0; off>>=1) s2 += __shfl_xor_sync(0xffffffffu, s2, off);
    if ((t&31)==0) red[t>>5] = s2;
    __syncthreads();
    if (t < 8){
        float x = red[t];
        x += __shfl_xor_sync(0xffu, x, 1);
        x += __shfl_xor_sync(0xffu, x, 2);
        x += __shfl_xor_sync(0xffu, x, 4);
        if (t==0) red[0] = x;
    }
    __syncthreads();
    const float var = red[0] * (1.0f/D_);
    const float rstd = rsqrtf(var + 1e-5f);
    out[(size_t)row*D_ + t] = d*rstd*g[t] + beta[t];
}

// =================== launch ===================
extern "C" void kernel_launch(void* const* d_in, const int* in_sizes, int n_in,
                              void* d_out, int out_size)
{
    const float* src = (const float*)d_in[0];
    const int*   adj = (const int*)  d_in[1];
    const float* Wq  = (const float*)d_in[2];  const float* bq  = (const float*)d_in[3];
    const float* Wk  = (const float*)d_in[4];  const float* bk  = (const float*)d_in[5];
    const float* Wv  = (const float*)d_in[6];  const float* bv  = (const float*)d_in[7];
    const float* Wo  = (const float*)d_in[8];  const float* bo  = (const float*)d_in[9];
    const float* W1  = (const float*)d_in[10]; const float* b1  = (const float*)d_in[11];
    const float* W2  = (const float*)d_in[12]; const float* b2  = (const float*)d_in[13];
    const float* g1  = (const float*)d_in[14]; const float* be1 = (const float*)d_in[15];
    const float* g2  = (const float*)d_in[16]; const float* be2 = (const float*)d_in[17];
    float* out = (float*)d_out;

    void* p;
    cudaGetSymbolAddress(&p, g_Qh);   __half* Qh = (__half*)p;
    cudaGetSymbolAddress(&p, g_Kh);   __half* Kh = (__half*)p;
    cudaGetSymbolAddress(&p, g_Vh);   __half* Vh = (__half*)p;
    cudaGetSymbolAddress(&p, g_adjB); unsigned char* adjB = (unsigned char*)p;
    cudaGetSymbolAddress(&p, g_O);    float* Ob = (float*)p;
    cudaGetSymbolAddress(&p, g_T1);   float* T1 = (float*)p;
    cudaGetSymbolAddress(&p, g_X);    float* Xb = (float*)p;
    cudaGetSymbolAddress(&p, g_F1);   float* F1 = (float*)p;
    cudaGetSymbolAddress(&p, g_T2);   float* T2 = (float*)p;

    const dim3 blk(256);

    // adj -> bytes (independent)
    adj2byte<<<(int)((size_t)M_*N_/4/256), blk>>>(adj, adjB);

    // batched Q/K/V projections, half output, Q pre-scaled
    QKVParams qp;
    qp.W[0]=Wq; qp.bias[0]=bq; qp.C[0]=Qh; qp.ldc[0]=D_;   qp.scale[0]=0.17677669529663688f;
    qp.W[1]=Wk; qp.bias[1]=bk; qp.C[1]=Kh; qp.ldc[1]=D_;   qp.scale[1]=1.f;
    for (int r=0;r<R_;r++){
        qp.W[2+r]=Wv + (size_t)r*D_*D_; qp.bias[2+r]=bv + r*D_;
        qp.C[2+r]=Vh + r*D_; qp.ldc[2+r]=R_*D_; qp.scale[2+r]=1.f;
    }
    gemm_qkv<<<dim3(D_/64, M_/128, 6), blk>>>(src, qp);

    // fused relational flash attention
    cudaFuncSetAttribute(attn_mma, cudaFuncAttributeMaxDynamicSharedMemorySize, ATTN_SMEM);
    attn_mma<<<dim3(N_/64, H_, B_), blk, ATTN_SMEM>>>(Qh, Kh, Vh, adjB, Ob);

    // output projection + LN1
    gemm_tc<false><<<dim3(D_/64, M_/128), blk>>>(Ob, Wo, bo, T1, D_, D_, D_);
    ln_kernel<<<M_, 256>>>(src, T1, g1, be1, Xb);

    // FFN + LN2
    gemm_tc<true ><<<dim3(FF_/64, M_/128), blk>>>(Xb, W1, b1, F1, FF_, D_, FF_);
    gemm_tc<false><<<dim3(D_/64, M_/128), blk>>>(F1, W2, b2, T2, D_, FF_, D_);
    ln_kernel<<<M_, 256>>>(Xb, T2, g2, be2, out);
}